// round 2
// baseline (speedup 1.0000x reference)
#include <cuda_runtime.h>
#include <cuda_bf16.h>
#include <cstdint>

// Problem dims
#define TT 2048
#define BB 16
#define DD 1024
static constexpr int MROWS = TT * BB;     // 32768
static constexpr int KDIM  = DD;          // 1024
static constexpr int NDIM  = 3 * DD;      // 3072

// ---------------- scratch (device globals: alloc-free rule) ----------------
__device__ float         g_pre[(size_t)MROWS * NDIM];          // 384 MB
__device__ __nv_bfloat16 g_wt_hi[(size_t)NDIM * KDIM];         // 6 MB
__device__ __nv_bfloat16 g_wt_lo[(size_t)NDIM * KDIM];         // 6 MB

// ---------------- helpers ----------------
__device__ __forceinline__ uint32_t smem_u32(const void* p) {
    uint32_t a;
    asm("{ .reg .u64 t; cvta.to.shared.u64 t, %1; cvt.u32.u64 %0, t; }" : "=r"(a) : "l"(p));
    return a;
}

#define SMEM_SWIZZLE_128B(o) ((o) ^ (((o) >> 3) & 0x70))

__device__ __forceinline__ void ldsm_x4(uint32_t addr, uint32_t* r) {
    asm volatile("ldmatrix.sync.aligned.m8n8.x4.shared.b16 {%0,%1,%2,%3}, [%4];"
        : "=r"(r[0]), "=r"(r[1]), "=r"(r[2]), "=r"(r[3]) : "r"(addr));
}
__device__ __forceinline__ void ldsm_x2(uint32_t addr, uint32_t* r) {
    asm volatile("ldmatrix.sync.aligned.m8n8.x2.shared.b16 {%0,%1}, [%2];"
        : "=r"(r[0]), "=r"(r[1]) : "r"(addr));
}
__device__ __forceinline__ void mma_bf16(float* c, const uint32_t* a, const uint32_t* b) {
    asm volatile("mma.sync.aligned.m16n8k16.row.col.f32.bf16.bf16.f32 "
        "{%0,%1,%2,%3}, {%4,%5,%6,%7}, {%8,%9}, {%0,%1,%2,%3};"
        : "+f"(c[0]), "+f"(c[1]), "+f"(c[2]), "+f"(c[3])
        : "r"(a[0]), "r"(a[1]), "r"(a[2]), "r"(a[3]), "r"(b[0]), "r"(b[1]));
}
__device__ __forceinline__ void cp_async16(uint32_t saddr, const void* gaddr) {
    asm volatile("cp.async.cg.shared.global [%0], [%1], 16;" :: "r"(saddr), "l"(gaddr));
}
#define CP_COMMIT() asm volatile("cp.async.commit_group;" ::: "memory")
#define CP_WAIT(n)  asm volatile("cp.async.wait_group %0;" :: "n"(n) : "memory")

__device__ __forceinline__ uint32_t pack_bf2(__nv_bfloat16 lo16, __nv_bfloat16 hi16) {
    return ((uint32_t)__bfloat16_as_ushort(hi16) << 16) | (uint32_t)__bfloat16_as_ushort(lo16);
}

// ---------------- kernel 1: W transpose + hi/lo bf16 split ----------------
__global__ void __launch_bounds__(256) wt_kernel(const float* __restrict__ W) {
    __shared__ float tile[32][33];
    int k0 = blockIdx.x * 32;        // K tiles: 1024/32
    int n0 = blockIdx.y * 32;        // N tiles: 3072/32
    int tx = threadIdx.x, ty = threadIdx.y;   // (32, 8)
#pragma unroll
    for (int i = 0; i < 4; i++) {
        int k = k0 + ty + i * 8;
        tile[ty + i * 8][tx] = W[(size_t)k * NDIM + n0 + tx];
    }
    __syncthreads();
#pragma unroll
    for (int i = 0; i < 4; i++) {
        int n = n0 + ty + i * 8;
        float v = tile[tx][ty + i * 8];
        __nv_bfloat16 h = __float2bfloat16(v);
        float rem = v - __bfloat162float(h);
        g_wt_hi[(size_t)n * KDIM + k0 + tx] = h;
        g_wt_lo[(size_t)n * KDIM + k0 + tx] = __float2bfloat16(rem);
    }
}

// ---------------- kernel 2: mma.sync split-bf16 GEMM ----------------
// Tile 128x128, BK=64, 8 warps (2 M x 4 N), warp tile 64x32, 2-stage pipeline.
static constexpr int ST_AHI = 0;
static constexpr int ST_ALO = 16384;
static constexpr int ST_BHI = 32768;
static constexpr int ST_BLO = 49152;
static constexpr int STAGE_BYTES = 65536;
static constexpr int GEMM_SMEM = 1024 + 2 * STAGE_BYTES;

__global__ void __launch_bounds__(256, 1) gemm_kernel(const float* __restrict__ A) {
    extern __shared__ char smem_raw[];
    uint32_t s0 = smem_u32(smem_raw);
    uint32_t base = (s0 + 1023) & ~1023u;
    char* sm = smem_raw + (base - s0);

    int tid = threadIdx.x;
    int lane = tid & 31, wid = tid >> 5;
    int wm = wid & 1, wn = wid >> 1;
    int ntile = blockIdx.x;     // 0..23
    int mtile = blockIdx.y;     // 0..255

    const float* Ab = A + (size_t)mtile * 128 * KDIM;
    const __nv_bfloat16* Bh = g_wt_hi + (size_t)ntile * 128 * KDIM;
    const __nv_bfloat16* Bl = g_wt_lo + (size_t)ntile * 128 * KDIM;

    // per-thread load geometry
    int a_r  = tid >> 4;          // A: rows step 16 (8 float4 per thread, +16 rows each)
    int a_c4 = tid & 15;
    int b_r  = tid >> 3;          // B: rows step 32 (4 chunks per thread)
    int b_q  = tid & 7;

    float4 av[8];

    // ---- helpers (lambdas) ----
    auto issueB = [&](int kc, int buf) {
        uint32_t stu = base + buf * STAGE_BYTES;
#pragma unroll
        for (int i = 0; i < 4; i++) {
            int r = b_r + i * 32;
            uint32_t sw = SMEM_SWIZZLE_128B((uint32_t)(r * 128 + b_q * 16));
            cp_async16(stu + ST_BHI + sw, Bh + (size_t)r * KDIM + kc * 64 + b_q * 8);
            cp_async16(stu + ST_BLO + sw, Bl + (size_t)r * KDIM + kc * 64 + b_q * 8);
        }
    };
    auto loadA = [&](int kc) {
        const float* Ak = Ab + kc * 64;
#pragma unroll
        for (int i = 0; i < 8; i++) {
            int r = a_r + i * 16;
            av[i] = *(const float4*)(Ak + (size_t)r * KDIM + a_c4 * 4);
        }
    };
    auto stsA = [&](int buf) {
        char* st = sm + buf * STAGE_BYTES;
#pragma unroll
        for (int i = 0; i < 8; i++) {
            int r = a_r + i * 16;
            float4 v = av[i];
            __nv_bfloat16 h0 = __float2bfloat16(v.x), h1 = __float2bfloat16(v.y);
            __nv_bfloat16 h2 = __float2bfloat16(v.z), h3 = __float2bfloat16(v.w);
            __nv_bfloat16 l0 = __float2bfloat16(v.x - __bfloat162float(h0));
            __nv_bfloat16 l1 = __float2bfloat16(v.y - __bfloat162float(h1));
            __nv_bfloat16 l2 = __float2bfloat16(v.z - __bfloat162float(h2));
            __nv_bfloat16 l3 = __float2bfloat16(v.w - __bfloat162float(h3));
            uint32_t sw = SMEM_SWIZZLE_128B((uint32_t)(r * 128 + a_c4 * 8));
            *(uint2*)(st + ST_AHI + sw) = make_uint2(pack_bf2(h0, h1), pack_bf2(h2, h3));
            *(uint2*)(st + ST_ALO + sw) = make_uint2(pack_bf2(l0, l1), pack_bf2(l2, l3));
        }
    };

    float acc[4][4][4];
#pragma unroll
    for (int i = 0; i < 4; i++)
#pragma unroll
        for (int j = 0; j < 4; j++)
#pragma unroll
            for (int k = 0; k < 4; k++) acc[i][j][k] = 0.f;

    // lane-level ldmatrix geometry
    int arow = wm * 64 + (lane & 15);
    int akoff = ((lane >> 4) & 1) * 16;
    int brow = wn * 32 + (lane & 7);
    int bkoff = ((lane >> 3) & 1) * 16;

    auto compute = [&](int buf) {
        uint32_t stu = base + buf * STAGE_BYTES;
#pragma unroll
        for (int s = 0; s < 4; s++) {
            uint32_t ah[4][4], al[4][4], bh[4][2], bl[4][2];
#pragma unroll
            for (int mi = 0; mi < 4; mi++) {
                uint32_t off = (uint32_t)((arow + mi * 16) * 128 + s * 32 + akoff);
                ldsm_x4(stu + ST_AHI + SMEM_SWIZZLE_128B(off), ah[mi]);
            }
#pragma unroll
            for (int ni = 0; ni < 4; ni++) {
                uint32_t off = (uint32_t)((brow + ni * 8) * 128 + s * 32 + bkoff);
                ldsm_x2(stu + ST_BHI + SMEM_SWIZZLE_128B(off), bh[ni]);
            }
#pragma unroll
            for (int mi = 0; mi < 4; mi++)
#pragma unroll
                for (int ni = 0; ni < 4; ni++) mma_bf16(acc[mi][ni], ah[mi], bh[ni]);
#pragma unroll
            for (int ni = 0; ni < 4; ni++) {
                uint32_t off = (uint32_t)((brow + ni * 8) * 128 + s * 32 + bkoff);
                ldsm_x2(stu + ST_BLO + SMEM_SWIZZLE_128B(off), bl[ni]);
            }
#pragma unroll
            for (int mi = 0; mi < 4; mi++)
#pragma unroll
                for (int ni = 0; ni < 4; ni++) mma_bf16(acc[mi][ni], ah[mi], bl[ni]);
#pragma unroll
            for (int mi = 0; mi < 4; mi++) {
                uint32_t off = (uint32_t)((arow + mi * 16) * 128 + s * 32 + akoff);
                ldsm_x4(stu + ST_ALO + SMEM_SWIZZLE_128B(off), al[mi]);
            }
#pragma unroll
            for (int mi = 0; mi < 4; mi++)
#pragma unroll
                for (int ni = 0; ni < 4; ni++) mma_bf16(acc[mi][ni], al[mi], bh[ni]);
        }
    };

    // ---- prologue ----
    issueB(0, 0); CP_COMMIT();
    loadA(0);
    issueB(1, 1); CP_COMMIT();
    stsA(0);
    loadA(1);
    CP_WAIT(1);                 // B(0) complete
    __syncthreads();

    // ---- main loop ----
    for (int kc = 0; kc < 16; kc++) {
        int buf = kc & 1;
        if (kc + 1 < 16) stsA(buf ^ 1);       // A(kc+1) regs -> other buffer
        if (kc + 2 < 16) loadA(kc + 2);       // prefetch A(kc+2)
        compute(buf);
        if (kc + 1 < 16) {
            CP_WAIT(0);                       // B(kc+1) complete
            __syncthreads();
            if (kc + 2 < 16) { issueB(kc + 2, buf); CP_COMMIT(); }
        }
    }

    // ---- epilogue: write acc to g_pre ----
    int g = lane >> 2, t = lane & 3;
    float* outp = g_pre + (size_t)(mtile * 128 + wm * 64) * NDIM + ntile * 128 + wn * 32;
#pragma unroll
    for (int mi = 0; mi < 4; mi++) {
#pragma unroll
        for (int ni = 0; ni < 4; ni++) {
            float* p0 = outp + (size_t)(mi * 16 + g) * NDIM + ni * 8 + 2 * t;
            *(float2*)p0 = make_float2(acc[mi][ni][0], acc[mi][ni][1]);
            *(float2*)(p0 + (size_t)8 * NDIM) = make_float2(acc[mi][ni][2], acc[mi][ni][3]);
        }
    }
}

// ---------------- kernel 3: LayerNorm + gate transform (in-place) ----------------
__global__ void __launch_bounds__(256) ln_kernel(const float* __restrict__ gamma,
                                                 const float* __restrict__ beta) {
    __shared__ float y[NDIM];
    __shared__ float red_s[8], red_q[8];
    __shared__ float s_mu, s_rstd;
    int row = blockIdx.x;
    float* pr = g_pre + (size_t)row * NDIM;
    int tid = threadIdx.x;
    int wid = tid >> 5, lid = tid & 31;
    float sum = 0.f, sq = 0.f;
#pragma unroll
    for (int i = 0; i < 12; i++) {
        float v = pr[tid + i * 256];
        y[tid + i * 256] = v;
        sum += v; sq += v * v;
    }
#pragma unroll
    for (int o = 16; o > 0; o >>= 1) {
        sum += __shfl_xor_sync(0xFFFFFFFFu, sum, o);
        sq  += __shfl_xor_sync(0xFFFFFFFFu, sq, o);
    }
    if (lid == 0) { red_s[wid] = sum; red_q[wid] = sq; }
    __syncthreads();
    if (tid == 0) {
        float s = 0.f, q = 0.f;
#pragma unroll
        for (int i = 0; i < 8; i++) { s += red_s[i]; q += red_q[i]; }
        float mu = s * (1.0f / NDIM);
        float var = q * (1.0f / NDIM) - mu * mu;
        s_mu = mu;
        s_rstd = rsqrtf(var + 1e-5f);
    }
    __syncthreads();
    float mu = s_mu, rstd = s_rstd;
#pragma unroll
    for (int i = 0; i < 4; i++) {
        int d = tid + i * 256;
        float y0 = (y[d]        - mu) * rstd * gamma[d]        + beta[d];
        float y1 = (y[d + 1024] - mu) * rstd * gamma[d + 1024] + beta[d + 1024];
        float y2 = (y[d + 2048] - mu) * rstd * gamma[d + 2048] + beta[d + 2048];
        float e = expf(-y0);
        float gg = 1.0f / (1.0f + e);    // sigmoid(y0)
        float a = e * gg;                // 1 - sigmoid(y0)
        float hg = 1.0f / (1.0f + expf(-y2));
        pr[d]        = a;
        pr[d + 1024] = gg * y1;
        pr[d + 2048] = hg;
    }
}

// ---------------- kernel 4: bidirectional scan + output mix ----------------
__global__ void __launch_bounds__(256) scan_kernel(const float* __restrict__ inp,
                                                   float* __restrict__ out) {
    int cid = blockIdx.x * 256 + threadIdx.x;   // 0..16383
    int b = cid >> 10;
    int d = cid & 1023;
    bool fwd = d < 512;
    int t = fwd ? 0 : (TT - 1);
    int step = fwd ? 1 : -1;
    float h = 0.f;
    const float* pr = g_pre;
#pragma unroll 4
    for (int it = 0; it < TT; it++) {
        size_t m = (size_t)(t * BB + b);
        size_t o = m * NDIM + d;
        float a  = pr[o];
        float bb = pr[o + 1024];
        float hg = pr[o + 2048];
        size_t oi = m * 1024 + d;
        float xi = inp[oi];
        h = fmaf(a, h, bb);
        out[oi] = fmaf(hg, xi - h, h);   // (1-hg)*h + xi*hg
        t += step;
    }
}

// ---------------- launch ----------------
extern "C" void kernel_launch(void* const* d_in, const int* in_sizes, int n_in,
                              void* d_out, int out_size) {
    const float* inp   = (const float*)d_in[0];
    const float* W     = (const float*)d_in[1];
    const float* gamma = (const float*)d_in[2];
    const float* beta  = (const float*)d_in[3];
    float* out = (float*)d_out;

    cudaFuncSetAttribute(gemm_kernel, cudaFuncAttributeMaxDynamicSharedMemorySize, GEMM_SMEM);

    wt_kernel<<<dim3(32, 96), dim3(32, 8)>>>(W);
    gemm_kernel<<<dim3(24, 256), 256, GEMM_SMEM>>>(inp);
    ln_kernel<<<MROWS, 256>>>(gamma, beta);
    scan_kernel<<<64, 256>>>(inp, out);
}

// round 3
// speedup vs baseline: 1.9001x; 1.9001x over previous
#include <cuda_runtime.h>
#include <cuda_fp16.h>
#include <cstdint>

// Problem dims
#define TT 2048
#define BB 16
#define DD 1024
static constexpr int MROWS = TT * BB;     // 32768
static constexpr int KDIM  = DD;          // 1024
static constexpr int NDIM  = 3 * DD;      // 3072

// scan chunking
static constexpr int NCH  = 32;           // chunks along T
static constexpr int CLEN = TT / NCH;     // 64
static constexpr int NCHAN = BB * DD;     // 16384 channels

// ---------------- scratch (device globals: alloc-free rule) ----------------
__device__ float  g_pre[(size_t)MROWS * NDIM];        // 384 MB
__device__ __half g_wh[(size_t)NDIM * KDIM];          // 6 MB  (W^T hi, fp16)
__device__ __half g_wl[(size_t)NDIM * KDIM];          // 6 MB  (W^T lo, fp16)
__device__ __half g_a16[(size_t)MROWS * KDIM];        // 64 MB (A fp16)
__device__ float  g_P[(size_t)NCH * NCHAN];           // 2 MB
__device__ float  g_S[(size_t)NCH * NCHAN];           // 2 MB
__device__ float  g_H[(size_t)NCH * NCHAN];           // 2 MB

// ---------------- helpers ----------------
__device__ __forceinline__ uint32_t smem_u32(const void* p) {
    uint32_t a;
    asm("{ .reg .u64 t; cvta.to.shared.u64 t, %1; cvt.u32.u64 %0, t; }" : "=r"(a) : "l"(p));
    return a;
}
#define SWZ(o) ((o) ^ (((o) >> 3) & 0x70))

__device__ __forceinline__ void ldsm_x4(uint32_t addr, uint32_t* r) {
    asm volatile("ldmatrix.sync.aligned.m8n8.x4.shared.b16 {%0,%1,%2,%3}, [%4];"
        : "=r"(r[0]), "=r"(r[1]), "=r"(r[2]), "=r"(r[3]) : "r"(addr));
}
__device__ __forceinline__ void mma_f16(float* c, const uint32_t* a, const uint32_t* b) {
    asm volatile("mma.sync.aligned.m16n8k16.row.col.f32.f16.f16.f32 "
        "{%0,%1,%2,%3}, {%4,%5,%6,%7}, {%8,%9}, {%0,%1,%2,%3};"
        : "+f"(c[0]), "+f"(c[1]), "+f"(c[2]), "+f"(c[3])
        : "r"(a[0]), "r"(a[1]), "r"(a[2]), "r"(a[3]), "r"(b[0]), "r"(b[1]));
}
__device__ __forceinline__ void cp_async16(uint32_t saddr, const void* gaddr) {
    asm volatile("cp.async.cg.shared.global [%0], [%1], 16;" :: "r"(saddr), "l"(gaddr));
}
#define CP_COMMIT() asm volatile("cp.async.commit_group;" ::: "memory")
#define CP_WAIT(n)  asm volatile("cp.async.wait_group %0;" :: "n"(n) : "memory")

// ---------------- kernel 1: W transpose + hi/lo fp16 split ----------------
__global__ void __launch_bounds__(256) wt_kernel(const float* __restrict__ W) {
    __shared__ float tile[32][33];
    int k0 = blockIdx.x * 32;        // 1024/32
    int n0 = blockIdx.y * 32;        // 3072/32
    int tx = threadIdx.x, ty = threadIdx.y;   // (32, 8)
#pragma unroll
    for (int i = 0; i < 4; i++) {
        int k = k0 + ty + i * 8;
        tile[ty + i * 8][tx] = W[(size_t)k * NDIM + n0 + tx];
    }
    __syncthreads();
#pragma unroll
    for (int i = 0; i < 4; i++) {
        int n = n0 + ty + i * 8;
        float v = tile[tx][ty + i * 8];
        __half h = __float2half_rn(v);
        float rem = v - __half2float(h);
        g_wh[(size_t)n * KDIM + k0 + tx] = h;
        g_wl[(size_t)n * KDIM + k0 + tx] = __float2half_rn(rem);
    }
}

// ---------------- kernel 2: A fp32 -> fp16 ----------------
__global__ void __launch_bounds__(1024) a16_kernel(const float* __restrict__ A) {
    size_t idx = (size_t)blockIdx.x * 1024 + threadIdx.x;   // float4 index
    float4 v = ((const float4*)A)[idx];
    __half2 h01 = __floats2half2_rn(v.x, v.y);
    __half2 h23 = __floats2half2_rn(v.z, v.w);
    uint2 u;
    u.x = *(uint32_t*)&h01;
    u.y = *(uint32_t*)&h23;
    ((uint2*)g_a16)[idx] = u;
}

// ---------------- kernel 3: fp16 2-pass GEMM (tile 128x256, BK=64) ----------------
static constexpr int ST_A  = 0;        // 128x64 fp16 = 16KB
static constexpr int ST_BH = 16384;    // 256x64 fp16 = 32KB
static constexpr int ST_BL = 49152;    // 32KB
static constexpr int STAGE_BYTES = 81920;
static constexpr int GEMM_SMEM = 1024 + 2 * STAGE_BYTES;

__global__ void __launch_bounds__(512, 1) gemm_kernel() {
    extern __shared__ char smem_raw[];
    uint32_t s0 = smem_u32(smem_raw);
    uint32_t base = (s0 + 1023) & ~1023u;

    int tid = threadIdx.x;
    int lane = tid & 31, wid = tid >> 5;
    int wm = wid & 3, wn = wid >> 2;          // 4 x 4 warps, warp tile 32x64
    int ntile = blockIdx.x;                   // 0..11
    int mtile = blockIdx.y;                   // 0..255
    int m0 = mtile * 128;

    const __half* Bh = g_wh + (size_t)ntile * 256 * KDIM;
    const __half* Bl = g_wl + (size_t)ntile * 256 * KDIM;

    auto issue = [&](int kc, int buf) {
        uint32_t stu = base + buf * STAGE_BYTES;
#pragma unroll
        for (int i = 0; i < 2; i++) {          // A: 1024 16B chunks
            int fid = tid + i * 512;
            int r = fid >> 3, q = fid & 7;
            uint32_t sw = SWZ((uint32_t)(r * 128 + q * 16));
            cp_async16(stu + ST_A + sw, g_a16 + (size_t)(m0 + r) * KDIM + kc * 64 + q * 8);
        }
#pragma unroll
        for (int i = 0; i < 4; i++) {          // B hi/lo: 2048 chunks each
            int fid = tid + i * 512;
            int r = fid >> 3, q = fid & 7;
            uint32_t sw = SWZ((uint32_t)(r * 128 + q * 16));
            cp_async16(stu + ST_BH + sw, Bh + (size_t)r * KDIM + kc * 64 + q * 8);
            cp_async16(stu + ST_BL + sw, Bl + (size_t)r * KDIM + kc * 64 + q * 8);
        }
    };

    float acc[2][8][4];
#pragma unroll
    for (int i = 0; i < 2; i++)
#pragma unroll
        for (int j = 0; j < 8; j++)
#pragma unroll
            for (int k = 0; k < 4; k++) acc[i][j][k] = 0.f;

    // lane geometry
    int a_row = wm * 32 + (lane & 15);
    int a_kb  = ((lane >> 4) & 1) * 16;
    int b_row = wn * 64 + (lane & 7) + ((lane >> 4) & 1) * 8;
    int b_kb  = ((lane >> 3) & 1) * 16;

    auto compute = [&](int buf) {
        uint32_t stu = base + buf * STAGE_BYTES;
#pragma unroll
        for (int s = 0; s < 4; s++) {
            uint32_t ah[2][4];
#pragma unroll
            for (int mi = 0; mi < 2; mi++) {
                uint32_t off = (uint32_t)((a_row + mi * 16) * 128 + s * 32 + a_kb);
                ldsm_x4(stu + ST_A + SWZ(off), ah[mi]);
            }
            uint32_t bh[4][4];
#pragma unroll
            for (int nj = 0; nj < 4; nj++) {
                uint32_t off = (uint32_t)((b_row + nj * 16) * 128 + s * 32 + b_kb);
                ldsm_x4(stu + ST_BH + SWZ(off), bh[nj]);
            }
#pragma unroll
            for (int mi = 0; mi < 2; mi++)
#pragma unroll
                for (int n8 = 0; n8 < 8; n8++)
                    mma_f16(acc[mi][n8], ah[mi], &bh[n8 >> 1][(n8 & 1) * 2]);
            uint32_t bl[4][4];
#pragma unroll
            for (int nj = 0; nj < 4; nj++) {
                uint32_t off = (uint32_t)((b_row + nj * 16) * 128 + s * 32 + b_kb);
                ldsm_x4(stu + ST_BL + SWZ(off), bl[nj]);
            }
#pragma unroll
            for (int mi = 0; mi < 2; mi++)
#pragma unroll
                for (int n8 = 0; n8 < 8; n8++)
                    mma_f16(acc[mi][n8], ah[mi], &bl[n8 >> 1][(n8 & 1) * 2]);
        }
    };

    // prologue
    issue(0, 0); CP_COMMIT();
    issue(1, 1); CP_COMMIT();
    CP_WAIT(1);
    __syncthreads();

    for (int kc = 0; kc < 16; kc++) {
        int buf = kc & 1;
        compute(buf);
        __syncthreads();
        if (kc + 2 < 16) { issue(kc + 2, buf); CP_COMMIT(); }
        if (kc + 1 < 16) { CP_WAIT(1); __syncthreads(); }
    }

    // epilogue
    int g = lane >> 2, t4 = lane & 3;
    float* outp = g_pre + (size_t)(m0 + wm * 32) * NDIM + ntile * 256 + wn * 64;
#pragma unroll
    for (int mi = 0; mi < 2; mi++) {
#pragma unroll
        for (int n8 = 0; n8 < 8; n8++) {
            float* p0 = outp + (size_t)(mi * 16 + g) * NDIM + n8 * 8 + 2 * t4;
            *(float2*)p0 = make_float2(acc[mi][n8][0], acc[mi][n8][1]);
            *(float2*)(p0 + (size_t)8 * NDIM) = make_float2(acc[mi][n8][2], acc[mi][n8][3]);
        }
    }
}

// ---------------- kernel 4: LayerNorm + gate transform (in-place) ----------------
__global__ void __launch_bounds__(256) ln_kernel(const float* __restrict__ gamma,
                                                 const float* __restrict__ beta) {
    __shared__ float4 y4[768];
    __shared__ float red_s[8], red_q[8];
    __shared__ float s_mu, s_rstd;
    int row = blockIdx.x;
    float* pr = g_pre + (size_t)row * NDIM;
    int tid = threadIdx.x;
    int wid = tid >> 5, lid = tid & 31;
    float sum = 0.f, sq = 0.f;
#pragma unroll
    for (int i = 0; i < 3; i++) {
        int idx = tid + i * 256;
        float4 v = ((const float4*)pr)[idx];
        y4[idx] = v;
        sum += v.x + v.y + v.z + v.w;
        sq += v.x * v.x + v.y * v.y + v.z * v.z + v.w * v.w;
    }
#pragma unroll
    for (int o = 16; o > 0; o >>= 1) {
        sum += __shfl_xor_sync(0xFFFFFFFFu, sum, o);
        sq  += __shfl_xor_sync(0xFFFFFFFFu, sq, o);
    }
    if (lid == 0) { red_s[wid] = sum; red_q[wid] = sq; }
    __syncthreads();
    if (tid == 0) {
        float s = 0.f, q = 0.f;
#pragma unroll
        for (int i = 0; i < 8; i++) { s += red_s[i]; q += red_q[i]; }
        float mu = s * (1.0f / NDIM);
        float var = q * (1.0f / NDIM) - mu * mu;
        s_mu = mu;
        s_rstd = rsqrtf(var + 1e-5f);
    }
    __syncthreads();
    float mu = s_mu, rstd = s_rstd;
    const float4* G4 = (const float4*)gamma;
    const float4* B4 = (const float4*)beta;
    float4 v0 = y4[tid], v1 = y4[tid + 256], v2 = y4[tid + 512];
    float4 g0 = G4[tid], g1 = G4[tid + 256], g2 = G4[tid + 512];
    float4 b0 = B4[tid], b1 = B4[tid + 256], b2 = B4[tid + 512];
    float4 ra, rb, rh;
#pragma unroll
    for (int c = 0; c < 4; c++) {
        float y0 = ((&v0.x)[c] - mu) * rstd * (&g0.x)[c] + (&b0.x)[c];
        float y1 = ((&v1.x)[c] - mu) * rstd * (&g1.x)[c] + (&b1.x)[c];
        float y2 = ((&v2.x)[c] - mu) * rstd * (&g2.x)[c] + (&b2.x)[c];
        float e = __expf(-y0);
        float gg = 1.0f / (1.0f + e);    // sigmoid(y0)
        (&ra.x)[c] = e * gg;             // 1 - sigmoid(y0)
        (&rb.x)[c] = gg * y1;
        (&rh.x)[c] = 1.0f / (1.0f + __expf(-y2));
    }
    ((float4*)pr)[tid]       = ra;
    ((float4*)pr)[tid + 256] = rb;
    ((float4*)pr)[tid + 512] = rh;
}

// ---------------- kernel 5a: chunk-local scan (P = prod a, S = local h) ------
__global__ void __launch_bounds__(256) scan1_kernel() {
    int idx = blockIdx.x * 256 + threadIdx.x;   // (c, b, d)
    int d = idx & 1023;
    int rest = idx >> 10;
    int b = rest & 15;
    int c = rest >> 4;
    bool fwd = d < 512;
    int t = fwd ? (c * CLEN) : (TT - 1 - c * CLEN);
    int step = fwd ? 1 : -1;
    float h = 0.f, p = 1.f;
    const float* pr = g_pre;
#pragma unroll 8
    for (int i = 0; i < CLEN; i++) {
        size_t o = (size_t)(t * BB + b) * NDIM + d;
        float a  = pr[o];
        float bb = pr[o + 1024];
        h = fmaf(a, h, bb);
        p *= a;
        t += step;
    }
    g_P[idx] = p;
    g_S[idx] = h;
}

// ---------------- kernel 5b: combine chunk summaries -> chunk start states ---
__global__ void __launch_bounds__(256) scan2_kernel() {
    int cid = blockIdx.x * 256 + threadIdx.x;   // 0..16383: (b, d)
    int d = cid & 1023;
    int b = cid >> 10;
    float h = 0.f;
#pragma unroll
    for (int c = 0; c < NCH; c++) {
        int j = ((c * BB + b) << 10) + d;
        g_H[j] = h;
        h = fmaf(g_P[j], h, g_S[j]);
    }
}

// ---------------- kernel 5c: apply + output mix ----------------
__global__ void __launch_bounds__(256) scan3_kernel(const float* __restrict__ inp,
                                                    float* __restrict__ out) {
    int idx = blockIdx.x * 256 + threadIdx.x;
    int d = idx & 1023;
    int rest = idx >> 10;
    int b = rest & 15;
    int c = rest >> 4;
    bool fwd = d < 512;
    int t = fwd ? (c * CLEN) : (TT - 1 - c * CLEN);
    int step = fwd ? 1 : -1;
    float h = g_H[idx];
    const float* pr = g_pre;
#pragma unroll 8
    for (int i = 0; i < CLEN; i++) {
        size_t m = (size_t)(t * BB + b);
        size_t o = m * NDIM + d;
        float a  = pr[o];
        float bb = pr[o + 1024];
        float hg = pr[o + 2048];
        size_t oi = m * 1024 + d;
        float xi = inp[oi];
        h = fmaf(a, h, bb);
        out[oi] = fmaf(hg, xi - h, h);   // (1-hg)*h + xi*hg
        t += step;
    }
}

// ---------------- launch ----------------
extern "C" void kernel_launch(void* const* d_in, const int* in_sizes, int n_in,
                              void* d_out, int out_size) {
    const float* inp   = (const float*)d_in[0];
    const float* W     = (const float*)d_in[1];
    const float* gamma = (const float*)d_in[2];
    const float* beta  = (const float*)d_in[3];
    float* out = (float*)d_out;

    cudaFuncSetAttribute(gemm_kernel, cudaFuncAttributeMaxDynamicSharedMemorySize, GEMM_SMEM);

    wt_kernel<<<dim3(32, 96), dim3(32, 8)>>>(W);
    a16_kernel<<<(MROWS * KDIM / 4) / 1024, 1024>>>(inp);
    gemm_kernel<<<dim3(12, 256), 512, GEMM_SMEM>>>();
    ln_kernel<<<MROWS, 256>>>(gamma, beta);
    scan1_kernel<<<(NCH * NCHAN) / 256, 256>>>();
    scan2_kernel<<<NCHAN / 256, 256>>>();
    scan3_kernel<<<(NCH * NCHAN) / 256, 256>>>(inp, out);
}

// round 4
// speedup vs baseline: 2.8273x; 1.4880x over previous
#include <cuda_runtime.h>
#include <cuda_fp16.h>
#include <cstdint>

// Problem dims
#define TT 2048
#define BB 16
#define DD 1024
static constexpr int MROWS = TT * BB;     // 32768
static constexpr int KDIM  = DD;          // 1024
static constexpr int NDIM  = 3 * DD;      // 3072
static constexpr int NTILES = NDIM / 256; // 12

// scan chunking
static constexpr int NCH  = 32;           // chunks along T
static constexpr int CLEN = TT / NCH;     // 64
static constexpr int NCHAN = BB * DD;     // 16384 channels

// ---------------- scratch (device globals: alloc-free rule) ----------------
__device__ float  g_pre[(size_t)MROWS * NDIM];        // 384 MB (raw GEMM out)
__device__ __half g_wh[(size_t)NDIM * KDIM];          // 6 MB  (W^T fp16)
__device__ __half g_a16[(size_t)MROWS * KDIM];        // 64 MB (A fp16)
__device__ float  g_psum[(size_t)MROWS * NTILES * 2]; // 3 MB  (partial LN sums)
__device__ float2 g_stats[(size_t)MROWS];             // 256 KB (mu, rstd)
__device__ float  g_P[(size_t)NCH * NCHAN];           // 2 MB
__device__ float  g_S[(size_t)NCH * NCHAN];           // 2 MB
__device__ float  g_H[(size_t)NCH * NCHAN];           // 2 MB

// ---------------- helpers ----------------
__device__ __forceinline__ uint32_t smem_u32(const void* p) {
    uint32_t a;
    asm("{ .reg .u64 t; cvta.to.shared.u64 t, %1; cvt.u32.u64 %0, t; }" : "=r"(a) : "l"(p));
    return a;
}
#define SWZ(o) ((o) ^ (((o) >> 3) & 0x70))

__device__ __forceinline__ void ldsm_x4(uint32_t addr, uint32_t* r) {
    asm volatile("ldmatrix.sync.aligned.m8n8.x4.shared.b16 {%0,%1,%2,%3}, [%4];"
        : "=r"(r[0]), "=r"(r[1]), "=r"(r[2]), "=r"(r[3]) : "r"(addr));
}
__device__ __forceinline__ void mma_f16(float* c, const uint32_t* a, const uint32_t* b) {
    asm volatile("mma.sync.aligned.m16n8k16.row.col.f32.f16.f16.f32 "
        "{%0,%1,%2,%3}, {%4,%5,%6,%7}, {%8,%9}, {%0,%1,%2,%3};"
        : "+f"(c[0]), "+f"(c[1]), "+f"(c[2]), "+f"(c[3])
        : "r"(a[0]), "r"(a[1]), "r"(a[2]), "r"(a[3]), "r"(b[0]), "r"(b[1]));
}
__device__ __forceinline__ void cp_async16(uint32_t saddr, const void* gaddr) {
    asm volatile("cp.async.cg.shared.global [%0], [%1], 16;" :: "r"(saddr), "l"(gaddr));
}
#define CP_COMMIT() asm volatile("cp.async.commit_group;" ::: "memory")
#define CP_WAIT(n)  asm volatile("cp.async.wait_group %0;" :: "n"(n) : "memory")

__device__ __forceinline__ float sigmoidf_fast(float x) {
    return 1.0f / (1.0f + __expf(-x));
}

// ---------------- kernel 1: W transpose -> fp16 ----------------
__global__ void __launch_bounds__(256) wt_kernel(const float* __restrict__ W) {
    __shared__ float tile[32][33];
    int k0 = blockIdx.x * 32;        // 1024/32
    int n0 = blockIdx.y * 32;        // 3072/32
    int tx = threadIdx.x, ty = threadIdx.y;   // (32, 8)
#pragma unroll
    for (int i = 0; i < 4; i++) {
        int k = k0 + ty + i * 8;
        tile[ty + i * 8][tx] = W[(size_t)k * NDIM + n0 + tx];
    }
    __syncthreads();
#pragma unroll
    for (int i = 0; i < 4; i++) {
        int n = n0 + ty + i * 8;
        g_wh[(size_t)n * KDIM + k0 + tx] = __float2half_rn(tile[tx][ty + i * 8]);
    }
}

// ---------------- kernel 2: A fp32 -> fp16 ----------------
__global__ void __launch_bounds__(1024) a16_kernel(const float* __restrict__ A) {
    size_t idx = (size_t)blockIdx.x * 1024 + threadIdx.x;   // float4 index
    float4 v = ((const float4*)A)[idx];
    __half2 h01 = __floats2half2_rn(v.x, v.y);
    __half2 h23 = __floats2half2_rn(v.z, v.w);
    uint2 u;
    u.x = *(uint32_t*)&h01;
    u.y = *(uint32_t*)&h23;
    ((uint2*)g_a16)[idx] = u;
}

// ---------------- kernel 3: fp16 1-pass GEMM (tile 128x256, BK=64) + LN partials --
static constexpr int ST_A  = 0;        // 128x64 fp16 = 16KB
static constexpr int ST_B  = 16384;    // 256x64 fp16 = 32KB
static constexpr int STAGE_BYTES = 49152;
static constexpr int GEMM_SMEM = 1024 + 2 * STAGE_BYTES;

__global__ void __launch_bounds__(512, 1) gemm_kernel() {
    extern __shared__ char smem_raw[];
    uint32_t s0 = smem_u32(smem_raw);
    uint32_t base = (s0 + 1023) & ~1023u;
    char* smb = smem_raw + (base - s0);

    int tid = threadIdx.x;
    int lane = tid & 31, wid = tid >> 5;
    int wm = wid & 3, wn = wid >> 2;          // 4 x 4 warps, warp tile 32x64
    int ntile = blockIdx.x;                   // 0..11
    int mtile = blockIdx.y;                   // 0..255
    int m0 = mtile * 128;

    const __half* Bp = g_wh + (size_t)ntile * 256 * KDIM;

    auto issue = [&](int kc, int buf) {
        uint32_t stu = base + buf * STAGE_BYTES;
#pragma unroll
        for (int i = 0; i < 2; i++) {          // A: 1024 16B chunks
            int fid = tid + i * 512;
            int r = fid >> 3, q = fid & 7;
            uint32_t sw = SWZ((uint32_t)(r * 128 + q * 16));
            cp_async16(stu + ST_A + sw, g_a16 + (size_t)(m0 + r) * KDIM + kc * 64 + q * 8);
        }
#pragma unroll
        for (int i = 0; i < 4; i++) {          // B: 2048 chunks
            int fid = tid + i * 512;
            int r = fid >> 3, q = fid & 7;
            uint32_t sw = SWZ((uint32_t)(r * 128 + q * 16));
            cp_async16(stu + ST_B + sw, Bp + (size_t)r * KDIM + kc * 64 + q * 8);
        }
    };

    float acc[2][8][4];
#pragma unroll
    for (int i = 0; i < 2; i++)
#pragma unroll
        for (int j = 0; j < 8; j++)
#pragma unroll
            for (int k = 0; k < 4; k++) acc[i][j][k] = 0.f;

    // lane geometry
    int a_row = wm * 32 + (lane & 15);
    int a_kb  = ((lane >> 4) & 1) * 16;
    int b_row = wn * 64 + (lane & 7) + ((lane >> 4) & 1) * 8;
    int b_kb  = ((lane >> 3) & 1) * 16;

    auto compute = [&](int buf) {
        uint32_t stu = base + buf * STAGE_BYTES;
#pragma unroll
        for (int s = 0; s < 4; s++) {
            uint32_t ah[2][4];
#pragma unroll
            for (int mi = 0; mi < 2; mi++) {
                uint32_t off = (uint32_t)((a_row + mi * 16) * 128 + s * 32 + a_kb);
                ldsm_x4(stu + ST_A + SWZ(off), ah[mi]);
            }
            uint32_t bh[4][4];
#pragma unroll
            for (int nj = 0; nj < 4; nj++) {
                uint32_t off = (uint32_t)((b_row + nj * 16) * 128 + s * 32 + b_kb);
                ldsm_x4(stu + ST_B + SWZ(off), bh[nj]);
            }
#pragma unroll
            for (int mi = 0; mi < 2; mi++)
#pragma unroll
                for (int n8 = 0; n8 < 8; n8++)
                    mma_f16(acc[mi][n8], ah[mi], &bh[n8 >> 1][(n8 & 1) * 2]);
        }
    };

    // prologue
    issue(0, 0); CP_COMMIT();
    issue(1, 1); CP_COMMIT();
    CP_WAIT(1);
    __syncthreads();

    for (int kc = 0; kc < 16; kc++) {
        int buf = kc & 1;
        compute(buf);
        __syncthreads();
        if (kc + 2 < 16) { issue(kc + 2, buf); CP_COMMIT(); }
        if (kc + 1 < 16) { CP_WAIT(1); __syncthreads(); }
    }

    // ---- epilogue part 1: write pre ----
    int g = lane >> 2, t4 = lane & 3;
    float* outp = g_pre + (size_t)(m0 + wm * 32) * NDIM + ntile * 256 + wn * 64;
#pragma unroll
    for (int mi = 0; mi < 2; mi++) {
#pragma unroll
        for (int n8 = 0; n8 < 8; n8++) {
            float* p0 = outp + (size_t)(mi * 16 + g) * NDIM + n8 * 8 + 2 * t4;
            *(float2*)p0 = make_float2(acc[mi][n8][0], acc[mi][n8][1]);
            *(float2*)(p0 + (size_t)8 * NDIM) = make_float2(acc[mi][n8][2], acc[mi][n8][3]);
        }
    }

    // ---- epilogue part 2: deterministic LN partial sums over this 256-col tile ----
    // per-thread row slots: row = wm*32 + mi*16 + half*8 + g
    float rs[4], rq[4];
#pragma unroll
    for (int mi = 0; mi < 2; mi++) {
#pragma unroll
        for (int half = 0; half < 2; half++) {
            float s = 0.f, q = 0.f;
#pragma unroll
            for (int n8 = 0; n8 < 8; n8++) {
#pragma unroll
                for (int e = 0; e < 2; e++) {
                    float v = acc[mi][n8][half * 2 + e];
                    s += v; q += v * v;
                }
            }
            rs[mi * 2 + half] = s;
            rq[mi * 2 + half] = q;
        }
    }
    // reduce across t4 lanes (same g)
#pragma unroll
    for (int o = 1; o <= 2; o <<= 1) {
#pragma unroll
        for (int k = 0; k < 4; k++) {
            rs[k] += __shfl_xor_sync(0xFFFFFFFFu, rs[k], o);
            rq[k] += __shfl_xor_sync(0xFFFFFFFFu, rq[k], o);
        }
    }
    __syncthreads();   // smem tiles no longer needed
    float* part_s = (float*)smb;            // [4 wn][128 rows]
    float* part_q = part_s + 4 * 128;
    if (t4 == 0) {
#pragma unroll
        for (int k = 0; k < 4; k++) {
            int row = wm * 32 + (k >> 1) * 16 + (k & 1) * 8 + g;
            part_s[wn * 128 + row] = rs[k];
            part_q[wn * 128 + row] = rq[k];
        }
    }
    __syncthreads();
    if (tid < 128) {
        float s = part_s[tid] + part_s[128 + tid] + part_s[256 + tid] + part_s[384 + tid];
        float q = part_q[tid] + part_q[128 + tid] + part_q[256 + tid] + part_q[384 + tid];
        size_t o = ((size_t)(m0 + tid) * NTILES + ntile) * 2;
        g_psum[o] = s;
        g_psum[o + 1] = q;
    }
}

// ---------------- kernel 4: fold partials -> (mu, rstd) ----------------
__global__ void __launch_bounds__(256) musig_kernel() {
    int row = blockIdx.x * 256 + threadIdx.x;
    const float* p = g_psum + (size_t)row * NTILES * 2;
    float s = 0.f, q = 0.f;
#pragma unroll
    for (int i = 0; i < NTILES; i++) { s += p[2 * i]; q += p[2 * i + 1]; }
    float mu = s * (1.0f / NDIM);
    float var = q * (1.0f / NDIM) - mu * mu;
    g_stats[row] = make_float2(mu, rsqrtf(var + 1e-5f));
}

// ---------------- kernel 5a: chunk-local scan with fused LN+gates ----------
__global__ void __launch_bounds__(256) scan1_kernel(const float* __restrict__ gamma,
                                                    const float* __restrict__ beta) {
    int idx = blockIdx.x * 256 + threadIdx.x;   // (c, b, d)
    int d = idx & 1023;
    int rest = idx >> 10;
    int b = rest & 15;
    int c = rest >> 4;
    bool fwd = d < 512;
    int t = fwd ? (c * CLEN) : (TT - 1 - c * CLEN);
    int step = fwd ? 1 : -1;
    float ga0 = gamma[d], be0 = beta[d];
    float ga1 = gamma[d + 1024], be1 = beta[d + 1024];
    float h = 0.f, p = 1.f;
    const float* pr = g_pre;
#pragma unroll 4
    for (int i = 0; i < CLEN; i++) {
        int m = t * BB + b;
        float2 st = g_stats[m];
        size_t o = (size_t)m * NDIM + d;
        float y0 = (pr[o]        - st.x) * st.y * ga0 + be0;
        float y1 = (pr[o + 1024] - st.x) * st.y * ga1 + be1;
        float e = __expf(-y0);
        float gg = 1.0f / (1.0f + e);
        float a = e * gg;                 // 1 - sigmoid(y0)
        float bb = gg * y1;
        h = fmaf(a, h, bb);
        p *= a;
        t += step;
    }
    g_P[idx] = p;
    g_S[idx] = h;
}

// ---------------- kernel 5b: combine chunk summaries -> chunk start states ---
__global__ void __launch_bounds__(256) scan2_kernel() {
    int cid = blockIdx.x * 256 + threadIdx.x;   // 0..16383: (b, d)
    int d = cid & 1023;
    int b = cid >> 10;
    float h = 0.f;
#pragma unroll
    for (int c = 0; c < NCH; c++) {
        int j = ((c * BB + b) << 10) + d;
        g_H[j] = h;
        h = fmaf(g_P[j], h, g_S[j]);
    }
}

// ---------------- kernel 5c: apply + fused LN + output mix ----------------
__global__ void __launch_bounds__(256) scan3_kernel(const float* __restrict__ inp,
                                                    float* __restrict__ out,
                                                    const float* __restrict__ gamma,
                                                    const float* __restrict__ beta) {
    int idx = blockIdx.x * 256 + threadIdx.x;
    int d = idx & 1023;
    int rest = idx >> 10;
    int b = rest & 15;
    int c = rest >> 4;
    bool fwd = d < 512;
    int t = fwd ? (c * CLEN) : (TT - 1 - c * CLEN);
    int step = fwd ? 1 : -1;
    float ga0 = gamma[d], be0 = beta[d];
    float ga1 = gamma[d + 1024], be1 = beta[d + 1024];
    float ga2 = gamma[d + 2048], be2 = beta[d + 2048];
    float h = g_H[idx];
    const float* pr = g_pre;
#pragma unroll 4
    for (int i = 0; i < CLEN; i++) {
        int m = t * BB + b;
        float2 st = g_stats[m];
        size_t o = (size_t)m * NDIM + d;
        float y0 = (pr[o]        - st.x) * st.y * ga0 + be0;
        float y1 = (pr[o + 1024] - st.x) * st.y * ga1 + be1;
        float y2 = (pr[o + 2048] - st.x) * st.y * ga2 + be2;
        float e = __expf(-y0);
        float gg = 1.0f / (1.0f + e);
        float a = e * gg;
        float bb = gg * y1;
        float hg = sigmoidf_fast(y2);
        size_t oi = (size_t)m * 1024 + d;
        float xi = inp[oi];
        h = fmaf(a, h, bb);
        out[oi] = fmaf(hg, xi - h, h);   // (1-hg)*h + xi*hg
        t += step;
    }
}

// ---------------- launch ----------------
extern "C" void kernel_launch(void* const* d_in, const int* in_sizes, int n_in,
                              void* d_out, int out_size) {
    const float* inp   = (const float*)d_in[0];
    const float* W     = (const float*)d_in[1];
    const float* gamma = (const float*)d_in[2];
    const float* beta  = (const float*)d_in[3];
    float* out = (float*)d_out;

    cudaFuncSetAttribute(gemm_kernel, cudaFuncAttributeMaxDynamicSharedMemorySize, GEMM_SMEM);

    wt_kernel<<<dim3(32, 96), dim3(32, 8)>>>(W);
    a16_kernel<<<(MROWS * KDIM / 4) / 1024, 1024>>>(inp);
    gemm_kernel<<<dim3(12, 256), 512, GEMM_SMEM>>>();
    musig_kernel<<<MROWS / 256, 256>>>();
    scan1_kernel<<<(NCH * NCHAN) / 256, 256>>>(gamma, beta);
    scan2_kernel<<<NCHAN / 256, 256>>>();
    scan3_kernel<<<(NCH * NCHAN) / 256, 256>>>(inp, out, gamma, beta);
}

// round 5
// speedup vs baseline: 2.9026x; 1.0266x over previous
#include <cuda_runtime.h>
#include <cuda_fp16.h>
#include <cstdint>

// Problem dims
#define TT 2048
#define BB 16
#define DD 1024
static constexpr int MROWS = TT * BB;     // 32768
static constexpr int KDIM  = DD;          // 1024
static constexpr int NDIM  = 3 * DD;      // 3072
static constexpr int NTILES = NDIM / 256; // 12

// scan chunking
static constexpr int NCH  = 32;           // chunks along T
static constexpr int CLEN = TT / NCH;     // 64
static constexpr int NCHAN = BB * DD;     // 16384 channels

// ---------------- scratch (device globals: alloc-free rule) ----------------
__device__ __half g_pre16[(size_t)MROWS * NDIM];      // 192 MB (fp16 GEMM out)
__device__ __half g_wh[(size_t)NDIM * KDIM];          // 6 MB  (W^T fp16)
__device__ __half g_a16[(size_t)MROWS * KDIM];        // 64 MB (A fp16)
__device__ float  g_psum[(size_t)MROWS * NTILES * 2]; // 3 MB  (partial LN sums)
__device__ float2 g_stats[(size_t)MROWS];             // 256 KB (mu, rstd)
__device__ float  g_P[(size_t)NCH * NCHAN];           // 2 MB
__device__ float  g_S[(size_t)NCH * NCHAN];           // 2 MB
__device__ float  g_H[(size_t)NCH * NCHAN];           // 2 MB

// ---------------- helpers ----------------
__device__ __forceinline__ uint32_t smem_u32(const void* p) {
    uint32_t a;
    asm("{ .reg .u64 t; cvta.to.shared.u64 t, %1; cvt.u32.u64 %0, t; }" : "=r"(a) : "l"(p));
    return a;
}
#define SWZ(o) ((o) ^ (((o) >> 3) & 0x70))

__device__ __forceinline__ void ldsm_x4(uint32_t addr, uint32_t* r) {
    asm volatile("ldmatrix.sync.aligned.m8n8.x4.shared.b16 {%0,%1,%2,%3}, [%4];"
        : "=r"(r[0]), "=r"(r[1]), "=r"(r[2]), "=r"(r[3]) : "r"(addr));
}
__device__ __forceinline__ void mma_f16(float* c, const uint32_t* a, const uint32_t* b) {
    asm volatile("mma.sync.aligned.m16n8k16.row.col.f32.f16.f16.f32 "
        "{%0,%1,%2,%3}, {%4,%5,%6,%7}, {%8,%9}, {%0,%1,%2,%3};"
        : "+f"(c[0]), "+f"(c[1]), "+f"(c[2]), "+f"(c[3])
        : "r"(a[0]), "r"(a[1]), "r"(a[2]), "r"(a[3]), "r"(b[0]), "r"(b[1]));
}
__device__ __forceinline__ void cp_async16(uint32_t saddr, const void* gaddr) {
    asm volatile("cp.async.cg.shared.global [%0], [%1], 16;" :: "r"(saddr), "l"(gaddr));
}
#define CP_COMMIT() asm volatile("cp.async.commit_group;" ::: "memory")
#define CP_WAIT(n)  asm volatile("cp.async.wait_group %0;" :: "n"(n) : "memory")

// ---------------- kernel 1: W transpose -> fp16 ----------------
__global__ void __launch_bounds__(256) wt_kernel(const float* __restrict__ W) {
    __shared__ float tile[32][33];
    int k0 = blockIdx.x * 32;        // 1024/32
    int n0 = blockIdx.y * 32;        // 3072/32
    int tx = threadIdx.x, ty = threadIdx.y;   // (32, 8)
#pragma unroll
    for (int i = 0; i < 4; i++) {
        int k = k0 + ty + i * 8;
        tile[ty + i * 8][tx] = W[(size_t)k * NDIM + n0 + tx];
    }
    __syncthreads();
#pragma unroll
    for (int i = 0; i < 4; i++) {
        int n = n0 + ty + i * 8;
        g_wh[(size_t)n * KDIM + k0 + tx] = __float2half_rn(tile[tx][ty + i * 8]);
    }
}

// ---------------- kernel 2: A fp32 -> fp16 ----------------
__global__ void __launch_bounds__(1024) a16_kernel(const float* __restrict__ A) {
    size_t idx = (size_t)blockIdx.x * 1024 + threadIdx.x;   // float4 index
    float4 v = ((const float4*)A)[idx];
    __half2 h01 = __floats2half2_rn(v.x, v.y);
    __half2 h23 = __floats2half2_rn(v.z, v.w);
    uint2 u;
    u.x = *(uint32_t*)&h01;
    u.y = *(uint32_t*)&h23;
    ((uint2*)g_a16)[idx] = u;
}

// ---------------- kernel 3: fp16 GEMM (tile 128x256, BK=64) + LN partials ----
static constexpr int ST_A  = 0;        // 128x64 fp16 = 16KB
static constexpr int ST_B  = 16384;    // 256x64 fp16 = 32KB
static constexpr int STAGE_BYTES = 49152;
static constexpr int GEMM_SMEM = 1024 + 2 * STAGE_BYTES;

__global__ void __launch_bounds__(512, 1) gemm_kernel() {
    extern __shared__ char smem_raw[];
    uint32_t s0 = smem_u32(smem_raw);
    uint32_t base = (s0 + 1023) & ~1023u;
    char* smb = smem_raw + (base - s0);

    int tid = threadIdx.x;
    int lane = tid & 31, wid = tid >> 5;
    int wm = wid & 3, wn = wid >> 2;          // 4 x 4 warps, warp tile 32x64
    int ntile = blockIdx.x;                   // 0..11
    int mtile = blockIdx.y;                   // 0..255
    int m0 = mtile * 128;

    const __half* Bp = g_wh + (size_t)ntile * 256 * KDIM;

    auto issue = [&](int kc, int buf) {
        uint32_t stu = base + buf * STAGE_BYTES;
#pragma unroll
        for (int i = 0; i < 2; i++) {          // A: 1024 16B chunks
            int fid = tid + i * 512;
            int r = fid >> 3, q = fid & 7;
            uint32_t sw = SWZ((uint32_t)(r * 128 + q * 16));
            cp_async16(stu + ST_A + sw, g_a16 + (size_t)(m0 + r) * KDIM + kc * 64 + q * 8);
        }
#pragma unroll
        for (int i = 0; i < 4; i++) {          // B: 2048 chunks
            int fid = tid + i * 512;
            int r = fid >> 3, q = fid & 7;
            uint32_t sw = SWZ((uint32_t)(r * 128 + q * 16));
            cp_async16(stu + ST_B + sw, Bp + (size_t)r * KDIM + kc * 64 + q * 8);
        }
    };

    float acc[2][8][4];
#pragma unroll
    for (int i = 0; i < 2; i++)
#pragma unroll
        for (int j = 0; j < 8; j++)
#pragma unroll
            for (int k = 0; k < 4; k++) acc[i][j][k] = 0.f;

    // lane geometry
    int a_row = wm * 32 + (lane & 15);
    int a_kb  = ((lane >> 4) & 1) * 16;
    int b_row = wn * 64 + (lane & 7) + ((lane >> 4) & 1) * 8;
    int b_kb  = ((lane >> 3) & 1) * 16;

    auto compute = [&](int buf) {
        uint32_t stu = base + buf * STAGE_BYTES;
#pragma unroll
        for (int s = 0; s < 4; s++) {
            uint32_t ah[2][4];
#pragma unroll
            for (int mi = 0; mi < 2; mi++) {
                uint32_t off = (uint32_t)((a_row + mi * 16) * 128 + s * 32 + a_kb);
                ldsm_x4(stu + ST_A + SWZ(off), ah[mi]);
            }
            uint32_t bh[4][4];
#pragma unroll
            for (int nj = 0; nj < 4; nj++) {
                uint32_t off = (uint32_t)((b_row + nj * 16) * 128 + s * 32 + b_kb);
                ldsm_x4(stu + ST_B + SWZ(off), bh[nj]);
            }
#pragma unroll
            for (int mi = 0; mi < 2; mi++)
#pragma unroll
                for (int n8 = 0; n8 < 8; n8++)
                    mma_f16(acc[mi][n8], ah[mi], &bh[n8 >> 1][(n8 & 1) * 2]);
        }
    };

    // prologue
    issue(0, 0); CP_COMMIT();
    issue(1, 1); CP_COMMIT();
    CP_WAIT(1);
    __syncthreads();

    for (int kc = 0; kc < 16; kc++) {
        int buf = kc & 1;
        compute(buf);
        __syncthreads();
        if (kc + 2 < 16) { issue(kc + 2, buf); CP_COMMIT(); }
        if (kc + 1 < 16) { CP_WAIT(1); __syncthreads(); }
    }

    // ---- epilogue part 1: write pre (fp16) ----
    int g = lane >> 2, t4 = lane & 3;
    __half* outp = g_pre16 + (size_t)(m0 + wm * 32) * NDIM + ntile * 256 + wn * 64;
#pragma unroll
    for (int mi = 0; mi < 2; mi++) {
#pragma unroll
        for (int n8 = 0; n8 < 8; n8++) {
            __half* p0 = outp + (size_t)(mi * 16 + g) * NDIM + n8 * 8 + 2 * t4;
            *(__half2*)p0 = __floats2half2_rn(acc[mi][n8][0], acc[mi][n8][1]);
            *(__half2*)(p0 + (size_t)8 * NDIM) = __floats2half2_rn(acc[mi][n8][2], acc[mi][n8][3]);
        }
    }

    // ---- epilogue part 2: deterministic LN partial sums (from exact fp32 accs) ----
    float rs[4], rq[4];
#pragma unroll
    for (int mi = 0; mi < 2; mi++) {
#pragma unroll
        for (int half = 0; half < 2; half++) {
            float s = 0.f, q = 0.f;
#pragma unroll
            for (int n8 = 0; n8 < 8; n8++) {
#pragma unroll
                for (int e = 0; e < 2; e++) {
                    float v = acc[mi][n8][half * 2 + e];
                    s += v; q += v * v;
                }
            }
            rs[mi * 2 + half] = s;
            rq[mi * 2 + half] = q;
        }
    }
#pragma unroll
    for (int o = 1; o <= 2; o <<= 1) {
#pragma unroll
        for (int k = 0; k < 4; k++) {
            rs[k] += __shfl_xor_sync(0xFFFFFFFFu, rs[k], o);
            rq[k] += __shfl_xor_sync(0xFFFFFFFFu, rq[k], o);
        }
    }
    __syncthreads();   // smem tiles no longer needed
    float* part_s = (float*)smb;            // [4 wn][128 rows]
    float* part_q = part_s + 4 * 128;
    if (t4 == 0) {
#pragma unroll
        for (int k = 0; k < 4; k++) {
            int row = wm * 32 + (k >> 1) * 16 + (k & 1) * 8 + g;
            part_s[wn * 128 + row] = rs[k];
            part_q[wn * 128 + row] = rq[k];
        }
    }
    __syncthreads();
    if (tid < 128) {
        float s = part_s[tid] + part_s[128 + tid] + part_s[256 + tid] + part_s[384 + tid];
        float q = part_q[tid] + part_q[128 + tid] + part_q[256 + tid] + part_q[384 + tid];
        size_t o = ((size_t)(m0 + tid) * NTILES + ntile) * 2;
        g_psum[o] = s;
        g_psum[o + 1] = q;
    }
}

// ---------------- kernel 4: fold partials -> (mu, rstd) ----------------
__global__ void __launch_bounds__(256) musig_kernel() {
    int row = blockIdx.x * 256 + threadIdx.x;
    const float* p = g_psum + (size_t)row * NTILES * 2;
    float s = 0.f, q = 0.f;
#pragma unroll
    for (int i = 0; i < NTILES; i++) { s += p[2 * i]; q += p[2 * i + 1]; }
    float mu = s * (1.0f / NDIM);
    float var = q * (1.0f / NDIM) - mu * mu;
    g_stats[row] = make_float2(mu, rsqrtf(var + 1e-5f));
}

// ---------------- kernel 5a: chunk-local scan, 2 channels/thread ----------
__global__ void __launch_bounds__(256) scan1_kernel(const float* __restrict__ gamma,
                                                    const float* __restrict__ beta) {
    int gidx = blockIdx.x * 256 + threadIdx.x;  // (c, b, dp)  dp = d/2
    int dp = gidx & 511;
    int rest = gidx >> 9;
    int b = rest & 15;
    int c = rest >> 4;
    int d = dp * 2;
    bool fwd = d < 512;
    int t = fwd ? (c * CLEN) : (TT - 1 - c * CLEN);
    int step = fwd ? 1 : -1;
    float2 ga0 = *(const float2*)(gamma + d);
    float2 be0 = *(const float2*)(beta + d);
    float2 ga1 = *(const float2*)(gamma + d + 1024);
    float2 be1 = *(const float2*)(beta + d + 1024);
    float h0 = 0.f, h1 = 0.f, p0 = 1.f, p1 = 1.f;
    const __half2* pr = (const __half2*)g_pre16;
#pragma unroll 4
    for (int i = 0; i < CLEN; i++) {
        int m = t * BB + b;
        float2 st = g_stats[m];
        size_t o = ((size_t)m * NDIM + d) >> 1;
        float2 v0 = __half22float2(pr[o]);
        float2 v1 = __half22float2(pr[o + 512]);
        float y0a = (v0.x - st.x) * st.y * ga0.x + be0.x;
        float y0b = (v0.y - st.x) * st.y * ga0.y + be0.y;
        float y1a = (v1.x - st.x) * st.y * ga1.x + be1.x;
        float y1b = (v1.y - st.x) * st.y * ga1.y + be1.y;
        float ea = __expf(-y0a), eb = __expf(-y0b);
        float gga = 1.0f / (1.0f + ea), ggb = 1.0f / (1.0f + eb);
        float aa = ea * gga, ab = eb * ggb;
        h0 = fmaf(aa, h0, gga * y1a);
        h1 = fmaf(ab, h1, ggb * y1b);
        p0 *= aa;
        p1 *= ab;
        t += step;
    }
    int j = ((c * BB + b) << 10) + d;
    g_P[j] = p0; g_P[j + 1] = p1;
    g_S[j] = h0; g_S[j + 1] = h1;
}

// ---------------- kernel 5b: combine chunk summaries -> chunk start states ---
__global__ void __launch_bounds__(256) scan2_kernel() {
    int cid = blockIdx.x * 256 + threadIdx.x;   // 0..16383: (b, d)
    int d = cid & 1023;
    int b = cid >> 10;
    float h = 0.f;
#pragma unroll
    for (int c = 0; c < NCH; c++) {
        int j = ((c * BB + b) << 10) + d;
        g_H[j] = h;
        h = fmaf(g_P[j], h, g_S[j]);
    }
}

// ---------------- kernel 5c: apply + fused LN + output mix, 2 ch/thread ------
__global__ void __launch_bounds__(256) scan3_kernel(const float* __restrict__ inp,
                                                    float* __restrict__ out,
                                                    const float* __restrict__ gamma,
                                                    const float* __restrict__ beta) {
    int gidx = blockIdx.x * 256 + threadIdx.x;
    int dp = gidx & 511;
    int rest = gidx >> 9;
    int b = rest & 15;
    int c = rest >> 4;
    int d = dp * 2;
    bool fwd = d < 512;
    int t = fwd ? (c * CLEN) : (TT - 1 - c * CLEN);
    int step = fwd ? 1 : -1;
    float2 ga0 = *(const float2*)(gamma + d);
    float2 be0 = *(const float2*)(beta + d);
    float2 ga1 = *(const float2*)(gamma + d + 1024);
    float2 be1 = *(const float2*)(beta + d + 1024);
    float2 ga2 = *(const float2*)(gamma + d + 2048);
    float2 be2 = *(const float2*)(beta + d + 2048);
    int j = ((c * BB + b) << 10) + d;
    float h0 = g_H[j], h1 = g_H[j + 1];
    const __half2* pr = (const __half2*)g_pre16;
#pragma unroll 4
    for (int i = 0; i < CLEN; i++) {
        int m = t * BB + b;
        float2 st = g_stats[m];
        size_t o = ((size_t)m * NDIM + d) >> 1;
        float2 v0 = __half22float2(pr[o]);
        float2 v1 = __half22float2(pr[o + 512]);
        float2 v2 = __half22float2(pr[o + 1024]);
        float y0a = (v0.x - st.x) * st.y * ga0.x + be0.x;
        float y0b = (v0.y - st.x) * st.y * ga0.y + be0.y;
        float y1a = (v1.x - st.x) * st.y * ga1.x + be1.x;
        float y1b = (v1.y - st.x) * st.y * ga1.y + be1.y;
        float y2a = (v2.x - st.x) * st.y * ga2.x + be2.x;
        float y2b = (v2.y - st.x) * st.y * ga2.y + be2.y;
        float ea = __expf(-y0a), eb = __expf(-y0b);
        float gga = 1.0f / (1.0f + ea), ggb = 1.0f / (1.0f + eb);
        float aa = ea * gga, ab = eb * ggb;
        float hga = 1.0f / (1.0f + __expf(-y2a));
        float hgb = 1.0f / (1.0f + __expf(-y2b));
        size_t oi = (size_t)m * 1024 + d;
        float2 xi = *(const float2*)(inp + oi);
        h0 = fmaf(aa, h0, gga * y1a);
        h1 = fmaf(ab, h1, ggb * y1b);
        float2 r;
        r.x = fmaf(hga, xi.x - h0, h0);
        r.y = fmaf(hgb, xi.y - h1, h1);
        *(float2*)(out + oi) = r;
        t += step;
    }
}

// ---------------- launch ----------------
extern "C" void kernel_launch(void* const* d_in, const int* in_sizes, int n_in,
                              void* d_out, int out_size) {
    const float* inp   = (const float*)d_in[0];
    const float* W     = (const float*)d_in[1];
    const float* gamma = (const float*)d_in[2];
    const float* beta  = (const float*)d_in[3];
    float* out = (float*)d_out;

    cudaFuncSetAttribute(gemm_kernel, cudaFuncAttributeMaxDynamicSharedMemorySize, GEMM_SMEM);

    wt_kernel<<<dim3(32, 96), dim3(32, 8)>>>(W);
    a16_kernel<<<(MROWS * KDIM / 4) / 1024, 1024>>>(inp);
    gemm_kernel<<<dim3(12, 256), 512, GEMM_SMEM>>>();
    musig_kernel<<<MROWS / 256, 256>>>();
    scan1_kernel<<<(NCH * NCHAN / 2) / 256, 256>>>(gamma, beta);
    scan2_kernel<<<NCHAN / 256, 256>>>();
    scan3_kernel<<<(NCH * NCHAN / 2) / 256, 256>>>(inp, out, gamma, beta);
}

// round 6
// speedup vs baseline: 2.9487x; 1.0159x over previous
#include <cuda_runtime.h>
#include <cuda_fp16.h>
#include <cstdint>

// Problem dims
#define TT 2048
#define BB 16
#define DD 1024
static constexpr int MROWS = TT * BB;     // 32768
static constexpr int KDIM  = DD;          // 1024
static constexpr int NDIM  = 3 * DD;      // 3072
static constexpr int NTILES = NDIM / 256; // 12

// scan chunking
static constexpr int NCH  = 32;           // chunks along T
static constexpr int CLEN = TT / NCH;     // 64
static constexpr int NCHAN = BB * DD;     // 16384 channels

// ---------------- scratch (device globals: alloc-free rule) ----------------
__device__ __half g_pre16[(size_t)MROWS * NDIM];      // 192 MB (fp16 GEMM out)
__device__ __half g_wh[(size_t)NDIM * KDIM];          // 6 MB  (W^T fp16)
__device__ __half g_a16[(size_t)MROWS * KDIM];        // 64 MB (A fp16)
__device__ float  g_psum[(size_t)MROWS * NTILES * 2]; // 3 MB  (partial LN sums)
__device__ float2 g_stats[(size_t)MROWS];             // 256 KB (mu, rstd)
__device__ float  g_P[(size_t)NCH * NCHAN];           // 2 MB
__device__ float  g_S[(size_t)NCH * NCHAN];           // 2 MB
__device__ float  g_H[(size_t)NCH * NCHAN];           // 2 MB

// ---------------- helpers ----------------
__device__ __forceinline__ uint32_t smem_u32(const void* p) {
    uint32_t a;
    asm("{ .reg .u64 t; cvta.to.shared.u64 t, %1; cvt.u32.u64 %0, t; }" : "=r"(a) : "l"(p));
    return a;
}
#define SWZ(o) ((o) ^ (((o) >> 3) & 0x70))

__device__ __forceinline__ void ldsm_x4(uint32_t addr, uint32_t* r) {
    asm volatile("ldmatrix.sync.aligned.m8n8.x4.shared.b16 {%0,%1,%2,%3}, [%4];"
        : "=r"(r[0]), "=r"(r[1]), "=r"(r[2]), "=r"(r[3]) : "r"(addr));
}
__device__ __forceinline__ void mma_f16(float* c, const uint32_t* a, const uint32_t* b) {
    asm volatile("mma.sync.aligned.m16n8k16.row.col.f32.f16.f16.f32 "
        "{%0,%1,%2,%3}, {%4,%5,%6,%7}, {%8,%9}, {%0,%1,%2,%3};"
        : "+f"(c[0]), "+f"(c[1]), "+f"(c[2]), "+f"(c[3])
        : "r"(a[0]), "r"(a[1]), "r"(a[2]), "r"(a[3]), "r"(b[0]), "r"(b[1]));
}
__device__ __forceinline__ void cp_async16(uint32_t saddr, const void* gaddr) {
    asm volatile("cp.async.cg.shared.global [%0], [%1], 16;" :: "r"(saddr), "l"(gaddr));
}
#define CP_COMMIT() asm volatile("cp.async.commit_group;" ::: "memory")
#define CP_WAIT(n)  asm volatile("cp.async.wait_group %0;" :: "n"(n) : "memory")

// ---------------- kernel 1: W transpose -> fp16 ----------------
__global__ void __launch_bounds__(256) wt_kernel(const float* __restrict__ W) {
    __shared__ float tile[32][33];
    int k0 = blockIdx.x * 32;        // 1024/32
    int n0 = blockIdx.y * 32;        // 3072/32
    int tx = threadIdx.x, ty = threadIdx.y;   // (32, 8)
#pragma unroll
    for (int i = 0; i < 4; i++) {
        int k = k0 + ty + i * 8;
        tile[ty + i * 8][tx] = W[(size_t)k * NDIM + n0 + tx];
    }
    __syncthreads();
#pragma unroll
    for (int i = 0; i < 4; i++) {
        int n = n0 + ty + i * 8;
        g_wh[(size_t)n * KDIM + k0 + tx] = __float2half_rn(tile[tx][ty + i * 8]);
    }
}

// ---------------- kernel 2: A fp32 -> fp16 ----------------
__global__ void __launch_bounds__(1024) a16_kernel(const float* __restrict__ A) {
    size_t idx = (size_t)blockIdx.x * 1024 + threadIdx.x;   // float4 index
    float4 v = ((const float4*)A)[idx];
    __half2 h01 = __floats2half2_rn(v.x, v.y);
    __half2 h23 = __floats2half2_rn(v.z, v.w);
    uint2 u;
    u.x = *(uint32_t*)&h01;
    u.y = *(uint32_t*)&h23;
    ((uint2*)g_a16)[idx] = u;
}

// ---------------- kernel 3: fp16 GEMM (tile 128x256, BK=64) + LN partials ----
// 3-stage cp.async pipeline, ONE barrier per K-iteration.
static constexpr int ST_A  = 0;        // 128x64 fp16 = 16KB
static constexpr int ST_B  = 16384;    // 256x64 fp16 = 32KB
static constexpr int STAGE_BYTES = 49152;
static constexpr int GEMM_SMEM = 1024 + 3 * STAGE_BYTES;   // ~145 KB

__global__ void __launch_bounds__(512, 1) gemm_kernel() {
    extern __shared__ char smem_raw[];
    uint32_t s0 = smem_u32(smem_raw);
    uint32_t base = (s0 + 1023) & ~1023u;
    char* smb = smem_raw + (base - s0);

    int tid = threadIdx.x;
    int lane = tid & 31, wid = tid >> 5;
    int wm = wid & 3, wn = wid >> 2;          // 4 x 4 warps, warp tile 32x64
    int ntile = blockIdx.x;                   // 0..11
    int mtile = blockIdx.y;                   // 0..255
    int m0 = mtile * 128;

    const __half* Bp = g_wh + (size_t)ntile * 256 * KDIM;

    auto issue = [&](int kc, int buf) {
        uint32_t stu = base + buf * STAGE_BYTES;
#pragma unroll
        for (int i = 0; i < 2; i++) {          // A: 1024 16B chunks
            int fid = tid + i * 512;
            int r = fid >> 3, q = fid & 7;
            uint32_t sw = SWZ((uint32_t)(r * 128 + q * 16));
            cp_async16(stu + ST_A + sw, g_a16 + (size_t)(m0 + r) * KDIM + kc * 64 + q * 8);
        }
#pragma unroll
        for (int i = 0; i < 4; i++) {          // B: 2048 chunks
            int fid = tid + i * 512;
            int r = fid >> 3, q = fid & 7;
            uint32_t sw = SWZ((uint32_t)(r * 128 + q * 16));
            cp_async16(stu + ST_B + sw, Bp + (size_t)r * KDIM + kc * 64 + q * 8);
        }
    };

    float acc[2][8][4];
#pragma unroll
    for (int i = 0; i < 2; i++)
#pragma unroll
        for (int j = 0; j < 8; j++)
#pragma unroll
            for (int k = 0; k < 4; k++) acc[i][j][k] = 0.f;

    // lane geometry
    int a_row = wm * 32 + (lane & 15);
    int a_kb  = ((lane >> 4) & 1) * 16;
    int b_row = wn * 64 + (lane & 7) + ((lane >> 4) & 1) * 8;
    int b_kb  = ((lane >> 3) & 1) * 16;

    auto compute = [&](int buf) {
        uint32_t stu = base + buf * STAGE_BYTES;
#pragma unroll
        for (int s = 0; s < 4; s++) {
            uint32_t ah[2][4];
#pragma unroll
            for (int mi = 0; mi < 2; mi++) {
                uint32_t off = (uint32_t)((a_row + mi * 16) * 128 + s * 32 + a_kb);
                ldsm_x4(stu + ST_A + SWZ(off), ah[mi]);
            }
            uint32_t bh[4][4];
#pragma unroll
            for (int nj = 0; nj < 4; nj++) {
                uint32_t off = (uint32_t)((b_row + nj * 16) * 128 + s * 32 + b_kb);
                ldsm_x4(stu + ST_B + SWZ(off), bh[nj]);
            }
#pragma unroll
            for (int mi = 0; mi < 2; mi++)
#pragma unroll
                for (int n8 = 0; n8 < 8; n8++)
                    mma_f16(acc[mi][n8], ah[mi], &bh[n8 >> 1][(n8 & 1) * 2]);
        }
    };

    // prologue: stages 0 and 1 in flight
    issue(0, 0); CP_COMMIT();
    issue(1, 1); CP_COMMIT();

    // main loop: one barrier per iteration
    for (int kc = 0; kc < 16; kc++) {
        if (kc < 15) { CP_WAIT(1); } else { CP_WAIT(0); }   // stage kc data ready
        __syncthreads();   // data visible + all warps done with stage (kc+2)%3's old contents
        if (kc + 2 < 16) { issue(kc + 2, (kc + 2) % 3); CP_COMMIT(); }
        compute(kc % 3);
    }

    // ---- epilogue part 1: write pre (fp16) ----
    int g = lane >> 2, t4 = lane & 3;
    __half* outp = g_pre16 + (size_t)(m0 + wm * 32) * NDIM + ntile * 256 + wn * 64;
#pragma unroll
    for (int mi = 0; mi < 2; mi++) {
#pragma unroll
        for (int n8 = 0; n8 < 8; n8++) {
            __half* p0 = outp + (size_t)(mi * 16 + g) * NDIM + n8 * 8 + 2 * t4;
            *(__half2*)p0 = __floats2half2_rn(acc[mi][n8][0], acc[mi][n8][1]);
            *(__half2*)(p0 + (size_t)8 * NDIM) = __floats2half2_rn(acc[mi][n8][2], acc[mi][n8][3]);
        }
    }

    // ---- epilogue part 2: deterministic LN partial sums (from exact fp32 accs) ----
    float rs[4], rq[4];
#pragma unroll
    for (int mi = 0; mi < 2; mi++) {
#pragma unroll
        for (int half = 0; half < 2; half++) {
            float s = 0.f, q = 0.f;
#pragma unroll
            for (int n8 = 0; n8 < 8; n8++) {
#pragma unroll
                for (int e = 0; e < 2; e++) {
                    float v = acc[mi][n8][half * 2 + e];
                    s += v; q += v * v;
                }
            }
            rs[mi * 2 + half] = s;
            rq[mi * 2 + half] = q;
        }
    }
#pragma unroll
    for (int o = 1; o <= 2; o <<= 1) {
#pragma unroll
        for (int k = 0; k < 4; k++) {
            rs[k] += __shfl_xor_sync(0xFFFFFFFFu, rs[k], o);
            rq[k] += __shfl_xor_sync(0xFFFFFFFFu, rq[k], o);
        }
    }
    __syncthreads();   // smem tiles no longer needed
    float* part_s = (float*)smb;            // [4 wn][128 rows]
    float* part_q = part_s + 4 * 128;
    if (t4 == 0) {
#pragma unroll
        for (int k = 0; k < 4; k++) {
            int row = wm * 32 + (k >> 1) * 16 + (k & 1) * 8 + g;
            part_s[wn * 128 + row] = rs[k];
            part_q[wn * 128 + row] = rq[k];
        }
    }
    __syncthreads();
    if (tid < 128) {
        float s = part_s[tid] + part_s[128 + tid] + part_s[256 + tid] + part_s[384 + tid];
        float q = part_q[tid] + part_q[128 + tid] + part_q[256 + tid] + part_q[384 + tid];
        size_t o = ((size_t)(m0 + tid) * NTILES + ntile) * 2;
        g_psum[o] = s;
        g_psum[o + 1] = q;
    }
}

// ---------------- kernel 4: fold partials -> (mu, rstd) ----------------
__global__ void __launch_bounds__(256) musig_kernel() {
    int row = blockIdx.x * 256 + threadIdx.x;
    const float* p = g_psum + (size_t)row * NTILES * 2;
    float s = 0.f, q = 0.f;
#pragma unroll
    for (int i = 0; i < NTILES; i++) { s += p[2 * i]; q += p[2 * i + 1]; }
    float mu = s * (1.0f / NDIM);
    float var = q * (1.0f / NDIM) - mu * mu;
    g_stats[row] = make_float2(mu, rsqrtf(var + 1e-5f));
}

// ---------------- kernel 5a: chunk-local scan, 2 channels/thread ----------
__global__ void __launch_bounds__(256) scan1_kernel(const float* __restrict__ gamma,
                                                    const float* __restrict__ beta) {
    int gidx = blockIdx.x * 256 + threadIdx.x;  // (c, b, dp)  dp = d/2
    int dp = gidx & 511;
    int rest = gidx >> 9;
    int b = rest & 15;
    int c = rest >> 4;
    int d = dp * 2;
    bool fwd = d < 512;
    int t = fwd ? (c * CLEN) : (TT - 1 - c * CLEN);
    int step = fwd ? 1 : -1;
    float2 ga0 = *(const float2*)(gamma + d);
    float2 be0 = *(const float2*)(beta + d);
    float2 ga1 = *(const float2*)(gamma + d + 1024);
    float2 be1 = *(const float2*)(beta + d + 1024);
    float h0 = 0.f, h1 = 0.f, p0 = 1.f, p1 = 1.f;
    const __half2* pr = (const __half2*)g_pre16;
#pragma unroll 8
    for (int i = 0; i < CLEN; i++) {
        int m = t * BB + b;
        float2 st = g_stats[m];
        size_t o = ((size_t)m * NDIM + d) >> 1;
        float2 v0 = __half22float2(pr[o]);
        float2 v1 = __half22float2(pr[o + 512]);
        float y0a = (v0.x - st.x) * st.y * ga0.x + be0.x;
        float y0b = (v0.y - st.x) * st.y * ga0.y + be0.y;
        float y1a = (v1.x - st.x) * st.y * ga1.x + be1.x;
        float y1b = (v1.y - st.x) * st.y * ga1.y + be1.y;
        float ea = __expf(-y0a), eb = __expf(-y0b);
        float gga = 1.0f / (1.0f + ea), ggb = 1.0f / (1.0f + eb);
        float aa = ea * gga, ab = eb * ggb;
        h0 = fmaf(aa, h0, gga * y1a);
        h1 = fmaf(ab, h1, ggb * y1b);
        p0 *= aa;
        p1 *= ab;
        t += step;
    }
    int j = ((c * BB + b) << 10) + d;
    g_P[j] = p0; g_P[j + 1] = p1;
    g_S[j] = h0; g_S[j + 1] = h1;
}

// ---------------- kernel 5b: combine chunk summaries -> chunk start states ---
__global__ void __launch_bounds__(256) scan2_kernel() {
    int cid = blockIdx.x * 256 + threadIdx.x;   // 0..16383: (b, d)
    int d = cid & 1023;
    int b = cid >> 10;
    float h = 0.f;
#pragma unroll
    for (int c = 0; c < NCH; c++) {
        int j = ((c * BB + b) << 10) + d;
        g_H[j] = h;
        h = fmaf(g_P[j], h, g_S[j]);
    }
}

// ---------------- kernel 5c: apply + fused LN + output mix, 2 ch/thread ------
__global__ void __launch_bounds__(256) scan3_kernel(const float* __restrict__ inp,
                                                    float* __restrict__ out,
                                                    const float* __restrict__ gamma,
                                                    const float* __restrict__ beta) {
    int gidx = blockIdx.x * 256 + threadIdx.x;
    int dp = gidx & 511;
    int rest = gidx >> 9;
    int b = rest & 15;
    int c = rest >> 4;
    int d = dp * 2;
    bool fwd = d < 512;
    int t = fwd ? (c * CLEN) : (TT - 1 - c * CLEN);
    int step = fwd ? 1 : -1;
    float2 ga0 = *(const float2*)(gamma + d);
    float2 be0 = *(const float2*)(beta + d);
    float2 ga1 = *(const float2*)(gamma + d + 1024);
    float2 be1 = *(const float2*)(beta + d + 1024);
    float2 ga2 = *(const float2*)(gamma + d + 2048);
    float2 be2 = *(const float2*)(beta + d + 2048);
    int j = ((c * BB + b) << 10) + d;
    float h0 = g_H[j], h1 = g_H[j + 1];
    const __half2* pr = (const __half2*)g_pre16;
#pragma unroll 8
    for (int i = 0; i < CLEN; i++) {
        int m = t * BB + b;
        float2 st = g_stats[m];
        size_t o = ((size_t)m * NDIM + d) >> 1;
        float2 v0 = __half22float2(pr[o]);
        float2 v1 = __half22float2(pr[o + 512]);
        float2 v2 = __half22float2(pr[o + 1024]);
        float y0a = (v0.x - st.x) * st.y * ga0.x + be0.x;
        float y0b = (v0.y - st.x) * st.y * ga0.y + be0.y;
        float y1a = (v1.x - st.x) * st.y * ga1.x + be1.x;
        float y1b = (v1.y - st.x) * st.y * ga1.y + be1.y;
        float y2a = (v2.x - st.x) * st.y * ga2.x + be2.x;
        float y2b = (v2.y - st.x) * st.y * ga2.y + be2.y;
        float ea = __expf(-y0a), eb = __expf(-y0b);
        float gga = 1.0f / (1.0f + ea), ggb = 1.0f / (1.0f + eb);
        float aa = ea * gga, ab = eb * ggb;
        float hga = 1.0f / (1.0f + __expf(-y2a));
        float hgb = 1.0f / (1.0f + __expf(-y2b));
        size_t oi = (size_t)m * 1024 + d;
        float2 xi = *(const float2*)(inp + oi);
        h0 = fmaf(aa, h0, gga * y1a);
        h1 = fmaf(ab, h1, ggb * y1b);
        float2 r;
        r.x = fmaf(hga, xi.x - h0, h0);
        r.y = fmaf(hgb, xi.y - h1, h1);
        *(float2*)(out + oi) = r;
        t += step;
    }
}

// ---------------- launch ----------------
extern "C" void kernel_launch(void* const* d_in, const int* in_sizes, int n_in,
                              void* d_out, int out_size) {
    const float* inp   = (const float*)d_in[0];
    const float* W     = (const float*)d_in[1];
    const float* gamma = (const float*)d_in[2];
    const float* beta  = (const float*)d_in[3];
    float* out = (float*)d_out;

    cudaFuncSetAttribute(gemm_kernel, cudaFuncAttributeMaxDynamicSharedMemorySize, GEMM_SMEM);

    wt_kernel<<<dim3(32, 96), dim3(32, 8)>>>(W);
    a16_kernel<<<(MROWS * KDIM / 4) / 1024, 1024>>>(inp);
    gemm_kernel<<<dim3(12, 256), 512, GEMM_SMEM>>>();
    musig_kernel<<<MROWS / 256, 256>>>();
    scan1_kernel<<<(NCH * NCHAN / 2) / 256, 256>>>(gamma, beta);
    scan2_kernel<<<NCHAN / 256, 256>>>();
    scan3_kernel<<<(NCH * NCHAN / 2) / 256, 256>>>(inp, out, gamma, beta);
}

// round 7
// speedup vs baseline: 3.1652x; 1.0734x over previous
#include <cuda_runtime.h>
#include <cuda_fp16.h>
#include <cstdint>

// Problem dims
#define TT 2048
#define BB 16
#define DD 1024
static constexpr int MROWS = TT * BB;     // 32768
static constexpr int KDIM  = DD;          // 1024
static constexpr int NDIM  = 3 * DD;      // 3072
static constexpr int NTILES = NDIM / 256; // 12

// scan chunking
static constexpr int NCH  = 32;           // chunks along T
static constexpr int CLEN = TT / NCH;     // 64
static constexpr int NCHAN = BB * DD;     // 16384 channels

// ---------------- scratch (device globals: alloc-free rule) ----------------
__device__ __half g_pre16[(size_t)MROWS * NDIM];      // 192 MB (fp16 GEMM out)
__device__ __half g_wh[(size_t)NDIM * KDIM];          // 6 MB  (W^T fp16)
__device__ __half g_a16[(size_t)MROWS * KDIM];        // 64 MB (A fp16)
__device__ float  g_psum[(size_t)MROWS * NTILES * 2]; // 3 MB  (partial LN sums)
__device__ float2 g_stats[(size_t)MROWS];             // 256 KB (mu, rstd)
__device__ float  g_P[(size_t)NCH * NCHAN];           // 2 MB
__device__ float  g_S[(size_t)NCH * NCHAN];           // 2 MB
__device__ float  g_H[(size_t)NCH * NCHAN];           // 2 MB

// ---------------- helpers ----------------
__device__ __forceinline__ uint32_t smem_u32(const void* p) {
    uint32_t a;
    asm("{ .reg .u64 t; cvta.to.shared.u64 t, %1; cvt.u32.u64 %0, t; }" : "=r"(a) : "l"(p));
    return a;
}
#define SWZ(o) ((o) ^ (((o) >> 3) & 0x70))

__device__ __forceinline__ void ldsm_x4(uint32_t addr, uint32_t* r) {
    asm volatile("ldmatrix.sync.aligned.m8n8.x4.shared.b16 {%0,%1,%2,%3}, [%4];"
        : "=r"(r[0]), "=r"(r[1]), "=r"(r[2]), "=r"(r[3]) : "r"(addr));
}
__device__ __forceinline__ void mma_f16(float* c, const uint32_t* a, const uint32_t* b) {
    asm volatile("mma.sync.aligned.m16n8k16.row.col.f32.f16.f16.f32 "
        "{%0,%1,%2,%3}, {%4,%5,%6,%7}, {%8,%9}, {%0,%1,%2,%3};"
        : "+f"(c[0]), "+f"(c[1]), "+f"(c[2]), "+f"(c[3])
        : "r"(a[0]), "r"(a[1]), "r"(a[2]), "r"(a[3]), "r"(b[0]), "r"(b[1]));
}
__device__ __forceinline__ void cp_async16(uint32_t saddr, const void* gaddr) {
    asm volatile("cp.async.cg.shared.global [%0], [%1], 16;" :: "r"(saddr), "l"(gaddr));
}
#define CP_COMMIT() asm volatile("cp.async.commit_group;" ::: "memory")
#define CP_WAIT(n)  asm volatile("cp.async.wait_group %0;" :: "n"(n) : "memory")

__device__ __forceinline__ void unpack4(uint2 u, float* v) {
    float2 a = __half22float2(*(__half2*)&u.x);
    float2 b = __half22float2(*(__half2*)&u.y);
    v[0] = a.x; v[1] = a.y; v[2] = b.x; v[3] = b.y;
}

// ---------------- kernel 1: W transpose -> fp16 ----------------
__global__ void __launch_bounds__(256) wt_kernel(const float* __restrict__ W) {
    __shared__ float tile[32][33];
    int k0 = blockIdx.x * 32;        // 1024/32
    int n0 = blockIdx.y * 32;        // 3072/32
    int tx = threadIdx.x, ty = threadIdx.y;   // (32, 8)
#pragma unroll
    for (int i = 0; i < 4; i++) {
        int k = k0 + ty + i * 8;
        tile[ty + i * 8][tx] = W[(size_t)k * NDIM + n0 + tx];
    }
    __syncthreads();
#pragma unroll
    for (int i = 0; i < 4; i++) {
        int n = n0 + ty + i * 8;
        g_wh[(size_t)n * KDIM + k0 + tx] = __float2half_rn(tile[tx][ty + i * 8]);
    }
}

// ---------------- kernel 2: A fp32 -> fp16 ----------------
__global__ void __launch_bounds__(1024) a16_kernel(const float* __restrict__ A) {
    size_t idx = (size_t)blockIdx.x * 1024 + threadIdx.x;   // float4 index
    float4 v = ((const float4*)A)[idx];
    __half2 h01 = __floats2half2_rn(v.x, v.y);
    __half2 h23 = __floats2half2_rn(v.z, v.w);
    uint2 u;
    u.x = *(uint32_t*)&h01;
    u.y = *(uint32_t*)&h23;
    ((uint2*)g_a16)[idx] = u;
}

// ---------------- kernel 3: fp16 GEMM (tile 128x256, BK=64, 8 warps 64x64) ---
// 3-stage cp.async pipeline, one barrier per K-iteration.
static constexpr int ST_A  = 0;        // 128x64 fp16 = 16KB
static constexpr int ST_B  = 16384;    // 256x64 fp16 = 32KB
static constexpr int STAGE_BYTES = 49152;
static constexpr int GEMM_SMEM = 1024 + 3 * STAGE_BYTES;   // ~145 KB

__global__ void __launch_bounds__(256, 1) gemm_kernel() {
    extern __shared__ char smem_raw[];
    uint32_t s0 = smem_u32(smem_raw);
    uint32_t base = (s0 + 1023) & ~1023u;
    char* smb = smem_raw + (base - s0);

    int tid = threadIdx.x;
    int lane = tid & 31, wid = tid >> 5;      // 8 warps
    int wm = wid & 1, wn = wid >> 1;          // 2 M x 4 N, warp tile 64x64
    int ntile = blockIdx.x;                   // 0..11
    int mtile = blockIdx.y;                   // 0..255
    int m0 = mtile * 128;

    const __half* Bp = g_wh + (size_t)ntile * 256 * KDIM;

    auto issue = [&](int kc, int buf) {
        uint32_t stu = base + buf * STAGE_BYTES;
#pragma unroll
        for (int i = 0; i < 4; i++) {          // A: 1024 16B chunks
            int fid = tid + i * 256;
            int r = fid >> 3, q = fid & 7;
            uint32_t sw = SWZ((uint32_t)(r * 128 + q * 16));
            cp_async16(stu + ST_A + sw, g_a16 + (size_t)(m0 + r) * KDIM + kc * 64 + q * 8);
        }
#pragma unroll
        for (int i = 0; i < 8; i++) {          // B: 2048 chunks
            int fid = tid + i * 256;
            int r = fid >> 3, q = fid & 7;
            uint32_t sw = SWZ((uint32_t)(r * 128 + q * 16));
            cp_async16(stu + ST_B + sw, Bp + (size_t)r * KDIM + kc * 64 + q * 8);
        }
    };

    float acc[4][8][4];
#pragma unroll
    for (int i = 0; i < 4; i++)
#pragma unroll
        for (int j = 0; j < 8; j++)
#pragma unroll
            for (int k = 0; k < 4; k++) acc[i][j][k] = 0.f;

    // lane geometry
    int a_row = wm * 64 + (lane & 15);
    int a_kb  = ((lane >> 4) & 1) * 16;
    int b_row = wn * 64 + (lane & 7) + ((lane >> 4) & 1) * 8;
    int b_kb  = ((lane >> 3) & 1) * 16;

    auto compute = [&](int buf) {
        uint32_t stu = base + buf * STAGE_BYTES;
#pragma unroll
        for (int s = 0; s < 4; s++) {
            uint32_t ah[4][4];
#pragma unroll
            for (int mi = 0; mi < 4; mi++) {
                uint32_t off = (uint32_t)((a_row + mi * 16) * 128 + s * 32 + a_kb);
                ldsm_x4(stu + ST_A + SWZ(off), ah[mi]);
            }
            uint32_t bh[4][4];
#pragma unroll
            for (int nj = 0; nj < 4; nj++) {
                uint32_t off = (uint32_t)((b_row + nj * 16) * 128 + s * 32 + b_kb);
                ldsm_x4(stu + ST_B + SWZ(off), bh[nj]);
            }
#pragma unroll
            for (int mi = 0; mi < 4; mi++)
#pragma unroll
                for (int n8 = 0; n8 < 8; n8++)
                    mma_f16(acc[mi][n8], ah[mi], &bh[n8 >> 1][(n8 & 1) * 2]);
        }
    };

    // prologue: stages 0 and 1 in flight
    issue(0, 0); CP_COMMIT();
    issue(1, 1); CP_COMMIT();

    // main loop: one barrier per iteration
    for (int kc = 0; kc < 16; kc++) {
        if (kc < 15) { CP_WAIT(1); } else { CP_WAIT(0); }
        __syncthreads();
        if (kc + 2 < 16) { issue(kc + 2, (kc + 2) % 3); CP_COMMIT(); }
        compute(kc % 3);
    }

    // ---- epilogue part 1: write pre (fp16) ----
    int g = lane >> 2, t4 = lane & 3;
    __half* outp = g_pre16 + (size_t)(m0 + wm * 64) * NDIM + ntile * 256 + wn * 64;
#pragma unroll
    for (int mi = 0; mi < 4; mi++) {
#pragma unroll
        for (int n8 = 0; n8 < 8; n8++) {
            __half* p0 = outp + (size_t)(mi * 16 + g) * NDIM + n8 * 8 + 2 * t4;
            *(__half2*)p0 = __floats2half2_rn(acc[mi][n8][0], acc[mi][n8][1]);
            *(__half2*)(p0 + (size_t)8 * NDIM) = __floats2half2_rn(acc[mi][n8][2], acc[mi][n8][3]);
        }
    }

    // ---- epilogue part 2: deterministic LN partial sums (from exact fp32 accs) ----
    // per-thread row slots: k = mi*2 + half -> row = wm*64 + mi*16 + half*8 + g
    float rs[8], rq[8];
#pragma unroll
    for (int mi = 0; mi < 4; mi++) {
#pragma unroll
        for (int half = 0; half < 2; half++) {
            float s = 0.f, q = 0.f;
#pragma unroll
            for (int n8 = 0; n8 < 8; n8++) {
#pragma unroll
                for (int e = 0; e < 2; e++) {
                    float v = acc[mi][n8][half * 2 + e];
                    s += v; q += v * v;
                }
            }
            rs[mi * 2 + half] = s;
            rq[mi * 2 + half] = q;
        }
    }
#pragma unroll
    for (int o = 1; o <= 2; o <<= 1) {
#pragma unroll
        for (int k = 0; k < 8; k++) {
            rs[k] += __shfl_xor_sync(0xFFFFFFFFu, rs[k], o);
            rq[k] += __shfl_xor_sync(0xFFFFFFFFu, rq[k], o);
        }
    }
    __syncthreads();   // smem tiles no longer needed
    float* part_s = (float*)smb;            // [4 wn][128 rows]
    float* part_q = part_s + 4 * 128;
    if (t4 == 0) {
#pragma unroll
        for (int k = 0; k < 8; k++) {
            int row = wm * 64 + (k >> 1) * 16 + (k & 1) * 8 + g;
            part_s[wn * 128 + row] = rs[k];
            part_q[wn * 128 + row] = rq[k];
        }
    }
    __syncthreads();
    if (tid < 128) {
        float s = part_s[tid] + part_s[128 + tid] + part_s[256 + tid] + part_s[384 + tid];
        float q = part_q[tid] + part_q[128 + tid] + part_q[256 + tid] + part_q[384 + tid];
        size_t o = ((size_t)(m0 + tid) * NTILES + ntile) * 2;
        g_psum[o] = s;
        g_psum[o + 1] = q;
    }
}

// ---------------- kernel 4: fold partials -> (mu, rstd) ----------------
__global__ void __launch_bounds__(256) musig_kernel() {
    int row = blockIdx.x * 256 + threadIdx.x;
    const float* p = g_psum + (size_t)row * NTILES * 2;
    float s = 0.f, q = 0.f;
#pragma unroll
    for (int i = 0; i < NTILES; i++) { s += p[2 * i]; q += p[2 * i + 1]; }
    float mu = s * (1.0f / NDIM);
    float var = q * (1.0f / NDIM) - mu * mu;
    g_stats[row] = make_float2(mu, rsqrtf(var + 1e-5f));
}

// ---------------- kernel 5a: chunk-local scan, 4 channels/thread ----------
__global__ void __launch_bounds__(256) scan1_kernel(const float* __restrict__ gamma,
                                                    const float* __restrict__ beta) {
    int gidx = blockIdx.x * 256 + threadIdx.x;  // (c, b, dq)  dq = d/4
    int dq = gidx & 255;
    int rest = gidx >> 8;
    int b = rest & 15;
    int c = rest >> 4;
    int d = dq * 4;
    bool fwd = d < 512;
    int t = fwd ? (c * CLEN) : (TT - 1 - c * CLEN);
    int step = fwd ? 1 : -1;
    float4 ga0 = *(const float4*)(gamma + d);
    float4 be0 = *(const float4*)(beta + d);
    float4 ga1 = *(const float4*)(gamma + d + 1024);
    float4 be1 = *(const float4*)(beta + d + 1024);
    float h[4] = {0.f, 0.f, 0.f, 0.f};
    float p[4] = {1.f, 1.f, 1.f, 1.f};
#pragma unroll 4
    for (int i = 0; i < CLEN; i++) {
        int m = t * BB + b;
        float2 st = g_stats[m];
        const __half* prm = g_pre16 + (size_t)m * NDIM + d;
        float v0[4], v1[4];
        unpack4(*(const uint2*)prm, v0);
        unpack4(*(const uint2*)(prm + 1024), v1);
#pragma unroll
        for (int j = 0; j < 4; j++) {
            float y0 = (v0[j] - st.x) * st.y * (&ga0.x)[j] + (&be0.x)[j];
            float y1 = (v1[j] - st.x) * st.y * (&ga1.x)[j] + (&be1.x)[j];
            float e = __expf(-y0);
            float gg = 1.0f / (1.0f + e);
            float a = e * gg;                  // 1 - sigmoid(y0)
            h[j] = fmaf(a, h[j], gg * y1);
            p[j] *= a;
        }
        t += step;
    }
    int j0 = ((c * BB + b) << 10) + d;
    *(float4*)(g_P + j0) = make_float4(p[0], p[1], p[2], p[3]);
    *(float4*)(g_S + j0) = make_float4(h[0], h[1], h[2], h[3]);
}

// ---------------- kernel 5b: combine chunk summaries -> chunk start states ---
__global__ void __launch_bounds__(256) scan2_kernel() {
    int cid = blockIdx.x * 256 + threadIdx.x;   // 0..16383: (b, d)
    int d = cid & 1023;
    int b = cid >> 10;
    float h = 0.f;
#pragma unroll
    for (int c = 0; c < NCH; c++) {
        int j = ((c * BB + b) << 10) + d;
        g_H[j] = h;
        h = fmaf(g_P[j], h, g_S[j]);
    }
}

// ---------------- kernel 5c: apply + fused LN + output mix, 4 ch/thread ------
__global__ void __launch_bounds__(256) scan3_kernel(const float* __restrict__ inp,
                                                    float* __restrict__ out,
                                                    const float* __restrict__ gamma,
                                                    const float* __restrict__ beta) {
    int gidx = blockIdx.x * 256 + threadIdx.x;
    int dq = gidx & 255;
    int rest = gidx >> 8;
    int b = rest & 15;
    int c = rest >> 4;
    int d = dq * 4;
    bool fwd = d < 512;
    int t = fwd ? (c * CLEN) : (TT - 1 - c * CLEN);
    int step = fwd ? 1 : -1;
    float4 ga0 = *(const float4*)(gamma + d);
    float4 be0 = *(const float4*)(beta + d);
    float4 ga1 = *(const float4*)(gamma + d + 1024);
    float4 be1 = *(const float4*)(beta + d + 1024);
    float4 ga2 = *(const float4*)(gamma + d + 2048);
    float4 be2 = *(const float4*)(beta + d + 2048);
    int j0 = ((c * BB + b) << 10) + d;
    float4 h4 = *(const float4*)(g_H + j0);
    float h[4] = {h4.x, h4.y, h4.z, h4.w};
#pragma unroll 4
    for (int i = 0; i < CLEN; i++) {
        int m = t * BB + b;
        float2 st = g_stats[m];
        const __half* prm = g_pre16 + (size_t)m * NDIM + d;
        float v0[4], v1[4], v2[4];
        unpack4(*(const uint2*)prm, v0);
        unpack4(*(const uint2*)(prm + 1024), v1);
        unpack4(*(const uint2*)(prm + 2048), v2);
        size_t oi = (size_t)m * 1024 + d;
        float4 xi = *(const float4*)(inp + oi);
        float4 r;
#pragma unroll
        for (int j = 0; j < 4; j++) {
            float y0 = (v0[j] - st.x) * st.y * (&ga0.x)[j] + (&be0.x)[j];
            float y1 = (v1[j] - st.x) * st.y * (&ga1.x)[j] + (&be1.x)[j];
            float y2 = (v2[j] - st.x) * st.y * (&ga2.x)[j] + (&be2.x)[j];
            float e = __expf(-y0);
            float gg = 1.0f / (1.0f + e);
            float a = e * gg;
            float hg = 1.0f / (1.0f + __expf(-y2));
            h[j] = fmaf(a, h[j], gg * y1);
            (&r.x)[j] = fmaf(hg, (&xi.x)[j] - h[j], h[j]);
        }
        *(float4*)(out + oi) = r;
        t += step;
    }
}

// ---------------- launch ----------------
extern "C" void kernel_launch(void* const* d_in, const int* in_sizes, int n_in,
                              void* d_out, int out_size) {
    const float* inp   = (const float*)d_in[0];
    const float* W     = (const float*)d_in[1];
    const float* gamma = (const float*)d_in[2];
    const float* beta  = (const float*)d_in[3];
    float* out = (float*)d_out;

    cudaFuncSetAttribute(gemm_kernel, cudaFuncAttributeMaxDynamicSharedMemorySize, GEMM_SMEM);

    wt_kernel<<<dim3(32, 96), dim3(32, 8)>>>(W);
    a16_kernel<<<(MROWS * KDIM / 4) / 1024, 1024>>>(inp);
    gemm_kernel<<<dim3(12, 256), 256, GEMM_SMEM>>>();
    musig_kernel<<<MROWS / 256, 256>>>();
    scan1_kernel<<<(NCH * NCHAN / 4) / 256, 256>>>(gamma, beta);
    scan2_kernel<<<NCHAN / 256, 256>>>();
    scan3_kernel<<<(NCH * NCHAN / 4) / 256, 256>>>(inp, out, gamma, beta);
}

// round 8
// speedup vs baseline: 3.5731x; 1.1289x over previous
#include <cuda_runtime.h>
#include <cuda_fp16.h>
#include <cstdint>

// Problem dims
#define TT 2048
#define BB 16
#define DD 1024
static constexpr int MROWS = TT * BB;     // 32768
static constexpr int KDIM  = DD;          // 1024
static constexpr int NDIM  = 3 * DD;      // 3072
static constexpr int NTILES = NDIM / 128; // 24

// scan chunking
static constexpr int NCH  = 32;           // chunks along T
static constexpr int CLEN = TT / NCH;     // 64
static constexpr int NCHAN = BB * DD;     // 16384 channels

// ---------------- scratch (device globals: alloc-free rule) ----------------
__device__ __half g_pre16[(size_t)MROWS * NDIM];      // 192 MB (fp16 GEMM out)
__device__ __half g_wh[(size_t)NDIM * KDIM];          // 6 MB  (W^T fp16)
__device__ __half g_a16[(size_t)MROWS * KDIM];        // 64 MB (A fp16)
__device__ float  g_psum[(size_t)MROWS * NTILES * 2]; // 6 MB  (partial LN sums)
__device__ float2 g_stats[(size_t)MROWS];             // 256 KB (mu, rstd)
__device__ float  g_P[(size_t)NCH * NCHAN];           // 2 MB
__device__ float  g_S[(size_t)NCH * NCHAN];           // 2 MB
__device__ float  g_H[(size_t)NCH * NCHAN];           // 2 MB

// ---------------- helpers ----------------
__device__ __forceinline__ uint32_t smem_u32(const void* p) {
    uint32_t a;
    asm("{ .reg .u64 t; cvta.to.shared.u64 t, %1; cvt.u32.u64 %0, t; }" : "=r"(a) : "l"(p));
    return a;
}
#define SWZ(o) ((o) ^ (((o) >> 3) & 0x70))

__device__ __forceinline__ void ldsm_x4(uint32_t addr, uint32_t* r) {
    asm volatile("ldmatrix.sync.aligned.m8n8.x4.shared.b16 {%0,%1,%2,%3}, [%4];"
        : "=r"(r[0]), "=r"(r[1]), "=r"(r[2]), "=r"(r[3]) : "r"(addr));
}
__device__ __forceinline__ void mma_f16(float* c, const uint32_t* a, const uint32_t* b) {
    asm volatile("mma.sync.aligned.m16n8k16.row.col.f32.f16.f16.f32 "
        "{%0,%1,%2,%3}, {%4,%5,%6,%7}, {%8,%9}, {%0,%1,%2,%3};"
        : "+f"(c[0]), "+f"(c[1]), "+f"(c[2]), "+f"(c[3])
        : "r"(a[0]), "r"(a[1]), "r"(a[2]), "r"(a[3]), "r"(b[0]), "r"(b[1]));
}
__device__ __forceinline__ void cp_async16(uint32_t saddr, const void* gaddr) {
    asm volatile("cp.async.cg.shared.global [%0], [%1], 16;" :: "r"(saddr), "l"(gaddr));
}
#define CP_COMMIT() asm volatile("cp.async.commit_group;" ::: "memory")
#define CP_WAIT(n)  asm volatile("cp.async.wait_group %0;" :: "n"(n) : "memory")

__device__ __forceinline__ void unpack4(uint2 u, float* v) {
    float2 a = __half22float2(*(__half2*)&u.x);
    float2 b = __half22float2(*(__half2*)&u.y);
    v[0] = a.x; v[1] = a.y; v[2] = b.x; v[3] = b.y;
}

__device__ __forceinline__ float tanh_fast(float x) {
    float r;
    asm("tanh.approx.f32 %0, %1;" : "=f"(r) : "f"(x));
    return r;
}
// sigmoid(x) = 0.5*tanh(x/2) + 0.5   (single MUFU)
__device__ __forceinline__ float sigmoid_fast(float x) {
    return fmaf(tanh_fast(0.5f * x), 0.5f, 0.5f);
}

// ---------------- kernel 1: W transpose -> fp16 ----------------
__global__ void __launch_bounds__(256) wt_kernel(const float* __restrict__ W) {
    __shared__ float tile[32][33];
    int k0 = blockIdx.x * 32;        // 1024/32
    int n0 = blockIdx.y * 32;        // 3072/32
    int tx = threadIdx.x, ty = threadIdx.y;   // (32, 8)
#pragma unroll
    for (int i = 0; i < 4; i++) {
        int k = k0 + ty + i * 8;
        tile[ty + i * 8][tx] = W[(size_t)k * NDIM + n0 + tx];
    }
    __syncthreads();
#pragma unroll
    for (int i = 0; i < 4; i++) {
        int n = n0 + ty + i * 8;
        g_wh[(size_t)n * KDIM + k0 + tx] = __float2half_rn(tile[tx][ty + i * 8]);
    }
}

// ---------------- kernel 2: A fp32 -> fp16 ----------------
__global__ void __launch_bounds__(1024) a16_kernel(const float* __restrict__ A) {
    size_t idx = (size_t)blockIdx.x * 1024 + threadIdx.x;   // float4 index
    float4 v = ((const float4*)A)[idx];
    __half2 h01 = __floats2half2_rn(v.x, v.y);
    __half2 h23 = __floats2half2_rn(v.z, v.w);
    uint2 u;
    u.x = *(uint32_t*)&h01;
    u.y = *(uint32_t*)&h23;
    ((uint2*)g_a16)[idx] = u;
}

// ---------------- kernel 3: fp16 GEMM (tile 128x128, BK=64, 4 warps 64x64) ---
// 3-stage cp.async pipeline, 2 CTAs/SM for epilogue overlap.
static constexpr int ST_A  = 0;        // 128x64 fp16 = 16KB
static constexpr int ST_B  = 16384;    // 128x64 fp16 = 16KB
static constexpr int STAGE_BYTES = 32768;
static constexpr int GEMM_SMEM = 1024 + 3 * STAGE_BYTES;   // ~97 KB

__global__ void __launch_bounds__(128, 2) gemm_kernel() {
    extern __shared__ char smem_raw[];
    uint32_t s0 = smem_u32(smem_raw);
    uint32_t base = (s0 + 1023) & ~1023u;
    char* smb = smem_raw + (base - s0);

    int tid = threadIdx.x;
    int lane = tid & 31, wid = tid >> 5;      // 4 warps
    int wm = wid & 1, wn = wid >> 1;          // 2 M x 2 N, warp tile 64x64
    int ntile = blockIdx.x;                   // 0..23
    int mtile = blockIdx.y;                   // 0..255
    int m0 = mtile * 128;

    const __half* Bp = g_wh + (size_t)ntile * 128 * KDIM;

    auto issue = [&](int kc, int buf) {
        uint32_t stu = base + buf * STAGE_BYTES;
#pragma unroll
        for (int i = 0; i < 8; i++) {          // A: 1024 16B chunks
            int fid = tid + i * 128;
            int r = fid >> 3, q = fid & 7;
            uint32_t sw = SWZ((uint32_t)(r * 128 + q * 16));
            cp_async16(stu + ST_A + sw, g_a16 + (size_t)(m0 + r) * KDIM + kc * 64 + q * 8);
        }
#pragma unroll
        for (int i = 0; i < 8; i++) {          // B: 1024 chunks
            int fid = tid + i * 128;
            int r = fid >> 3, q = fid & 7;
            uint32_t sw = SWZ((uint32_t)(r * 128 + q * 16));
            cp_async16(stu + ST_B + sw, Bp + (size_t)r * KDIM + kc * 64 + q * 8);
        }
    };

    float acc[4][8][4];
#pragma unroll
    for (int i = 0; i < 4; i++)
#pragma unroll
        for (int j = 0; j < 8; j++)
#pragma unroll
            for (int k = 0; k < 4; k++) acc[i][j][k] = 0.f;

    // lane geometry
    int a_row = wm * 64 + (lane & 15);
    int a_kb  = ((lane >> 4) & 1) * 16;
    int b_row = wn * 64 + (lane & 7) + ((lane >> 4) & 1) * 8;
    int b_kb  = ((lane >> 3) & 1) * 16;

    auto compute = [&](int buf) {
        uint32_t stu = base + buf * STAGE_BYTES;
#pragma unroll
        for (int s = 0; s < 4; s++) {
            uint32_t ah[4][4];
#pragma unroll
            for (int mi = 0; mi < 4; mi++) {
                uint32_t off = (uint32_t)((a_row + mi * 16) * 128 + s * 32 + a_kb);
                ldsm_x4(stu + ST_A + SWZ(off), ah[mi]);
            }
            uint32_t bh[4][4];
#pragma unroll
            for (int nj = 0; nj < 4; nj++) {
                uint32_t off = (uint32_t)((b_row + nj * 16) * 128 + s * 32 + b_kb);
                ldsm_x4(stu + ST_B + SWZ(off), bh[nj]);
            }
#pragma unroll
            for (int mi = 0; mi < 4; mi++)
#pragma unroll
                for (int n8 = 0; n8 < 8; n8++)
                    mma_f16(acc[mi][n8], ah[mi], &bh[n8 >> 1][(n8 & 1) * 2]);
        }
    };

    // prologue: stages 0 and 1 in flight
    issue(0, 0); CP_COMMIT();
    issue(1, 1); CP_COMMIT();

    // main loop: one barrier per iteration
    for (int kc = 0; kc < 16; kc++) {
        if (kc < 15) { CP_WAIT(1); } else { CP_WAIT(0); }
        __syncthreads();
        if (kc + 2 < 16) { issue(kc + 2, (kc + 2) % 3); CP_COMMIT(); }
        compute(kc % 3);
    }

    // ---- epilogue part 1: write pre (fp16) ----
    int g = lane >> 2, t4 = lane & 3;
    __half* outp = g_pre16 + (size_t)(m0 + wm * 64) * NDIM + ntile * 128 + wn * 64;
#pragma unroll
    for (int mi = 0; mi < 4; mi++) {
#pragma unroll
        for (int n8 = 0; n8 < 8; n8++) {
            __half* p0 = outp + (size_t)(mi * 16 + g) * NDIM + n8 * 8 + 2 * t4;
            *(__half2*)p0 = __floats2half2_rn(acc[mi][n8][0], acc[mi][n8][1]);
            *(__half2*)(p0 + (size_t)8 * NDIM) = __floats2half2_rn(acc[mi][n8][2], acc[mi][n8][3]);
        }
    }

    // ---- epilogue part 2: deterministic LN partial sums (from exact fp32 accs) ----
    // per-thread row slots: k = mi*2 + half -> row = wm*64 + mi*16 + half*8 + g
    float rs[8], rq[8];
#pragma unroll
    for (int mi = 0; mi < 4; mi++) {
#pragma unroll
        for (int half = 0; half < 2; half++) {
            float s = 0.f, q = 0.f;
#pragma unroll
            for (int n8 = 0; n8 < 8; n8++) {
#pragma unroll
                for (int e = 0; e < 2; e++) {
                    float v = acc[mi][n8][half * 2 + e];
                    s += v; q += v * v;
                }
            }
            rs[mi * 2 + half] = s;
            rq[mi * 2 + half] = q;
        }
    }
#pragma unroll
    for (int o = 1; o <= 2; o <<= 1) {
#pragma unroll
        for (int k = 0; k < 8; k++) {
            rs[k] += __shfl_xor_sync(0xFFFFFFFFu, rs[k], o);
            rq[k] += __shfl_xor_sync(0xFFFFFFFFu, rq[k], o);
        }
    }
    __syncthreads();   // smem tiles no longer needed
    float* part_s = (float*)smb;            // [2 wn][128 rows]
    float* part_q = part_s + 2 * 128;
    if (t4 == 0) {
#pragma unroll
        for (int k = 0; k < 8; k++) {
            int row = wm * 64 + (k >> 1) * 16 + (k & 1) * 8 + g;
            part_s[wn * 128 + row] = rs[k];
            part_q[wn * 128 + row] = rq[k];
        }
    }
    __syncthreads();
    if (tid < 128) {
        float s = part_s[tid] + part_s[128 + tid];
        float q = part_q[tid] + part_q[128 + tid];
        size_t o = ((size_t)(m0 + tid) * NTILES + ntile) * 2;
        g_psum[o] = s;
        g_psum[o + 1] = q;
    }
}

// ---------------- kernel 4: fold partials -> (mu, rstd) ----------------
__global__ void __launch_bounds__(256) musig_kernel() {
    int row = blockIdx.x * 256 + threadIdx.x;
    const float* p = g_psum + (size_t)row * NTILES * 2;
    float s = 0.f, q = 0.f;
#pragma unroll
    for (int i = 0; i < NTILES; i++) { s += p[2 * i]; q += p[2 * i + 1]; }
    float mu = s * (1.0f / NDIM);
    float var = q * (1.0f / NDIM) - mu * mu;
    g_stats[row] = make_float2(mu, rsqrtf(var + 1e-5f));
}

// ---------------- kernel 5a: chunk-local scan, 4 channels/thread ----------
__global__ void __launch_bounds__(256) scan1_kernel(const float* __restrict__ gamma,
                                                    const float* __restrict__ beta) {
    int gidx = blockIdx.x * 256 + threadIdx.x;  // (c, b, dq)  dq = d/4
    int dq = gidx & 255;
    int rest = gidx >> 8;
    int b = rest & 15;
    int c = rest >> 4;
    int d = dq * 4;
    bool fwd = d < 512;
    int t = fwd ? (c * CLEN) : (TT - 1 - c * CLEN);
    int step = fwd ? 1 : -1;
    float4 ga0 = *(const float4*)(gamma + d);
    float4 be0 = *(const float4*)(beta + d);
    float4 ga1 = *(const float4*)(gamma + d + 1024);
    float4 be1 = *(const float4*)(beta + d + 1024);
    float h[4] = {0.f, 0.f, 0.f, 0.f};
    float p[4] = {1.f, 1.f, 1.f, 1.f};
#pragma unroll 4
    for (int i = 0; i < CLEN; i++) {
        int m = t * BB + b;
        float2 st = g_stats[m];
        const __half* prm = g_pre16 + (size_t)m * NDIM + d;
        float v0[4], v1[4];
        unpack4(*(const uint2*)prm, v0);
        unpack4(*(const uint2*)(prm + 1024), v1);
#pragma unroll
        for (int j = 0; j < 4; j++) {
            float y0 = (v0[j] - st.x) * st.y * (&ga0.x)[j] + (&be0.x)[j];
            float y1 = (v1[j] - st.x) * st.y * (&ga1.x)[j] + (&be1.x)[j];
            float gg = sigmoid_fast(y0);
            float a = 1.0f - gg;
            h[j] = fmaf(a, h[j], gg * y1);
            p[j] *= a;
        }
        t += step;
    }
    int j0 = ((c * BB + b) << 10) + d;
    *(float4*)(g_P + j0) = make_float4(p[0], p[1], p[2], p[3]);
    *(float4*)(g_S + j0) = make_float4(h[0], h[1], h[2], h[3]);
}

// ---------------- kernel 5b: combine chunk summaries -> chunk start states ---
__global__ void __launch_bounds__(256) scan2_kernel() {
    int cid = blockIdx.x * 256 + threadIdx.x;   // 0..16383: (b, d)
    int d = cid & 1023;
    int b = cid >> 10;
    float h = 0.f;
#pragma unroll
    for (int c = 0; c < NCH; c++) {
        int j = ((c * BB + b) << 10) + d;
        g_H[j] = h;
        h = fmaf(g_P[j], h, g_S[j]);
    }
}

// ---------------- kernel 5c: apply + fused LN + output mix, 4 ch/thread ------
__global__ void __launch_bounds__(256) scan3_kernel(const float* __restrict__ inp,
                                                    float* __restrict__ out,
                                                    const float* __restrict__ gamma,
                                                    const float* __restrict__ beta) {
    int gidx = blockIdx.x * 256 + threadIdx.x;
    int dq = gidx & 255;
    int rest = gidx >> 8;
    int b = rest & 15;
    int c = rest >> 4;
    int d = dq * 4;
    bool fwd = d < 512;
    int t = fwd ? (c * CLEN) : (TT - 1 - c * CLEN);
    int step = fwd ? 1 : -1;
    float4 ga0 = *(const float4*)(gamma + d);
    float4 be0 = *(const float4*)(beta + d);
    float4 ga1 = *(const float4*)(gamma + d + 1024);
    float4 be1 = *(const float4*)(beta + d + 1024);
    float4 ga2 = *(const float4*)(gamma + d + 2048);
    float4 be2 = *(const float4*)(beta + d + 2048);
    int j0 = ((c * BB + b) << 10) + d;
    float4 h4 = *(const float4*)(g_H + j0);
    float h[4] = {h4.x, h4.y, h4.z, h4.w};
#pragma unroll 4
    for (int i = 0; i < CLEN; i++) {
        int m = t * BB + b;
        float2 st = g_stats[m];
        const __half* prm = g_pre16 + (size_t)m * NDIM + d;
        float v0[4], v1[4], v2[4];
        unpack4(*(const uint2*)prm, v0);
        unpack4(*(const uint2*)(prm + 1024), v1);
        unpack4(*(const uint2*)(prm + 2048), v2);
        size_t oi = (size_t)m * 1024 + d;
        float4 xi = *(const float4*)(inp + oi);
        float4 r;
#pragma unroll
        for (int j = 0; j < 4; j++) {
            float y0 = (v0[j] - st.x) * st.y * (&ga0.x)[j] + (&be0.x)[j];
            float y1 = (v1[j] - st.x) * st.y * (&ga1.x)[j] + (&be1.x)[j];
            float y2 = (v2[j] - st.x) * st.y * (&ga2.x)[j] + (&be2.x)[j];
            float gg = sigmoid_fast(y0);
            float a = 1.0f - gg;
            float hg = sigmoid_fast(y2);
            h[j] = fmaf(a, h[j], gg * y1);
            (&r.x)[j] = fmaf(hg, (&xi.x)[j] - h[j], h[j]);
        }
        *(float4*)(out + oi) = r;
        t += step;
    }
}

// ---------------- launch ----------------
extern "C" void kernel_launch(void* const* d_in, const int* in_sizes, int n_in,
                              void* d_out, int out_size) {
    const float* inp   = (const float*)d_in[0];
    const float* W     = (const float*)d_in[1];
    const float* gamma = (const float*)d_in[2];
    const float* beta  = (const float*)d_in[3];
    float* out = (float*)d_out;

    cudaFuncSetAttribute(gemm_kernel, cudaFuncAttributeMaxDynamicSharedMemorySize, GEMM_SMEM);

    wt_kernel<<<dim3(32, 96), dim3(32, 8)>>>(W);
    a16_kernel<<<(MROWS * KDIM / 4) / 1024, 1024>>>(inp);
    gemm_kernel<<<dim3(24, 256), 128, GEMM_SMEM>>>();
    musig_kernel<<<MROWS / 256, 256>>>();
    scan1_kernel<<<(NCH * NCHAN / 4) / 256, 256>>>(gamma, beta);
    scan2_kernel<<<NCHAN / 256, 256>>>();
    scan3_kernel<<<(NCH * NCHAN / 4) / 256, 256>>>(inp, out, gamma, beta);
}